// round 9
// baseline (speedup 1.0000x reference)
#include <cuda_runtime.h>
#include <cuda_bf16.h>
#include <cstdint>
#include <math.h>

#define BB 2
#define SS 2048
#define DD 1024
#define HH 16
#define HD 64

// Scratch: q,k,v head-major [B,H,S,HD]; attn output [B,S,D]
__device__ float g_q[BB*HH*SS*HD];
__device__ float g_k[BB*HH*SS*HD];
__device__ float g_v[BB*HH*SS*HD];
__device__ float g_attn[BB*SS*DD];

// ===========================================================================
// Helpers: ldmatrix / mma.sync bf16 / fp32 split-pack
// ===========================================================================
__device__ __forceinline__ uint32_t smem_u32(const void* p) {
    uint32_t a;
    asm("{ .reg .u64 t; cvta.to.shared.u64 t, %1; cvt.u32.u64 %0, t; }"
        : "=r"(a) : "l"(p));
    return a;
}
__device__ __forceinline__ void ldsm4(uint32_t* r, uint32_t a) {
    asm volatile("ldmatrix.sync.aligned.m8n8.x4.shared.b16 {%0,%1,%2,%3}, [%4];"
                 : "=r"(r[0]), "=r"(r[1]), "=r"(r[2]), "=r"(r[3]) : "r"(a));
}
__device__ __forceinline__ void ldsm4t(uint32_t* r, uint32_t a) {
    asm volatile("ldmatrix.sync.aligned.m8n8.x4.trans.shared.b16 {%0,%1,%2,%3}, [%4];"
                 : "=r"(r[0]), "=r"(r[1]), "=r"(r[2]), "=r"(r[3]) : "r"(a));
}
__device__ __forceinline__ void mma_bf(float* d, const uint32_t* a, const uint32_t* b) {
    asm volatile("mma.sync.aligned.m16n8k16.row.col.f32.bf16.bf16.f32 "
                 "{%0,%1,%2,%3}, {%4,%5,%6,%7}, {%8,%9}, {%0,%1,%2,%3};"
                 : "+f"(d[0]), "+f"(d[1]), "+f"(d[2]), "+f"(d[3])
                 : "r"(a[0]), "r"(a[1]), "r"(a[2]), "r"(a[3]),
                   "r"(b[0]), "r"(b[1]));
}
// pack the high (bf16-truncated) halves of two fp32: low bf16 = x, high = y
__device__ __forceinline__ uint32_t packhi(float x, float y) {
    uint32_t r;
    asm("prmt.b32 %0, %1, %2, 0x7632;"
        : "=r"(r) : "r"(__float_as_uint(x)), "r"(__float_as_uint(y)));
    return r;
}
// residuals (x - trunc_bf16(x)) rounded to bf16x2
__device__ __forceinline__ uint32_t packlo(float x, float y) {
    float lx = x - __uint_as_float(__float_as_uint(x) & 0xFFFF0000u);
    float ly = y - __uint_as_float(__float_as_uint(y) & 0xFFFF0000u);
    uint32_t r;
    asm("cvt.rn.bf16x2.f32 %0, %1, %2;" : "=r"(r) : "f"(ly), "f"(lx));
    return r;
}

// ===========================================================================
// NT GEMM via mma.sync bf16 3-term compensation:
//   C[m,n] = sum_k A[m,k]*W[n,k] + bias[n]
// Block 128x128x(BK=32). 8 warps: 4(m) x 2(n); warp tile 32m x 64n.
// Smem tiles (bf16): Ahi/Alo [128][32], Bhi/Blo [128][32]; 64B rows,
// granule swizzle g ^= (row & 3). Register prefetch of next k-slab.
// mode 0: head-major [B,H,S,HD] store; mode 1: plain [row,col].
// ===========================================================================
#define AHI 0
#define ALO 8192
#define BHI 16384
#define BLO 24576

__global__ __launch_bounds__(256) void gemm_mma(const float* __restrict__ A,
                                                const float* __restrict__ W,
                                                const float* __restrict__ bias,
                                                float* __restrict__ C, int mode)
{
    __shared__ char sh[32768];
    const uint32_t shb = smem_u32(sh);
    const int tid  = threadIdx.x;
    const int lane = tid & 31;
    const int wid  = tid >> 5;
    const int wm   = wid & 3;
    const int wn   = wid >> 2;
    const int m0   = blockIdx.y * 128;
    const int n0   = blockIdx.x * 128;

    const int frow = tid >> 1;           // 0..127 (tile row for fill)
    const int fcol = (tid & 1) * 16;     // 0 or 16 within the 32-wide k slab

    float acc[2][8][4];
#pragma unroll
    for (int mt = 0; mt < 2; ++mt)
#pragma unroll
        for (int nt = 0; nt < 8; ++nt)
#pragma unroll
            for (int e = 0; e < 4; ++e) acc[mt][nt][e] = 0.0f;

    float4 pa[4], pb[4];
#pragma unroll
    for (int i = 0; i < 4; ++i) {
        pa[i] = *(const float4*)&A[(size_t)(m0 + frow) * DD + fcol + i * 4];
        pb[i] = *(const float4*)&W[(size_t)(n0 + frow) * DD + fcol + i * 4];
    }

    for (int kb = 0; kb < DD / 32; ++kb) {
        __syncthreads();
        // ---- store prefetched slab, split hi/lo ----
#pragma unroll
        for (int gi = 0; gi < 2; ++gi) {
            const float* fa = (const float*)&pa[gi * 2];
            const float* fb = (const float*)&pb[gi * 2];
            int g = (tid & 1) * 2 + gi;
            uint32_t off = (uint32_t)frow * 64 + (((uint32_t)(g ^ (frow & 3))) << 4);
            uint4 h4, l4;
            h4.x = packhi(fa[0], fa[1]); h4.y = packhi(fa[2], fa[3]);
            h4.z = packhi(fa[4], fa[5]); h4.w = packhi(fa[6], fa[7]);
            l4.x = packlo(fa[0], fa[1]); l4.y = packlo(fa[2], fa[3]);
            l4.z = packlo(fa[4], fa[5]); l4.w = packlo(fa[6], fa[7]);
            *(uint4*)(sh + AHI + off) = h4;
            *(uint4*)(sh + ALO + off) = l4;
            h4.x = packhi(fb[0], fb[1]); h4.y = packhi(fb[2], fb[3]);
            h4.z = packhi(fb[4], fb[5]); h4.w = packhi(fb[6], fb[7]);
            l4.x = packlo(fb[0], fb[1]); l4.y = packlo(fb[2], fb[3]);
            l4.z = packlo(fb[4], fb[5]); l4.w = packlo(fb[6], fb[7]);
            *(uint4*)(sh + BHI + off) = h4;
            *(uint4*)(sh + BLO + off) = l4;
        }
        __syncthreads();

        // ---- prefetch next slab (latency hidden under mma) ----
        if (kb + 1 < DD / 32) {
            int kn = (kb + 1) * 32 + fcol;
#pragma unroll
            for (int i = 0; i < 4; ++i) {
                pa[i] = *(const float4*)&A[(size_t)(m0 + frow) * DD + kn + i * 4];
                pb[i] = *(const float4*)&W[(size_t)(n0 + frow) * DD + kn + i * 4];
            }
        }

        // ---- mma over the 2 k16 steps of this slab ----
#pragma unroll
        for (int ks = 0; ks < 2; ++ks) {
            uint32_t ah[2][4], al[2][4];
#pragma unroll
            for (int mt = 0; mt < 2; ++mt) {
                int r = wm * 32 + mt * 16 + (lane & 15);
                int g = ks * 2 + (lane >> 4);
                uint32_t off = (uint32_t)r * 64 + (((uint32_t)(g ^ (r & 3))) << 4);
                ldsm4(ah[mt], shb + AHI + off);
                ldsm4(al[mt], shb + ALO + off);
            }
#pragma unroll
            for (int np = 0; np < 4; ++np) {
                int r = wn * 64 + np * 16 + ((lane >> 4) << 3) + (lane & 7);
                int g = ks * 2 + ((lane >> 3) & 1);
                uint32_t off = (uint32_t)r * 64 + (((uint32_t)(g ^ (r & 3))) << 4);
                uint32_t bh4[4], bl4[4];
                ldsm4(bh4, shb + BHI + off);
                ldsm4(bl4, shb + BLO + off);
#pragma unroll
                for (int t = 0; t < 2; ++t) {
                    int nt = np * 2 + t;
#pragma unroll
                    for (int mt = 0; mt < 2; ++mt) {
                        mma_bf(acc[mt][nt], ah[mt], bh4 + t * 2);
                        mma_bf(acc[mt][nt], al[mt], bh4 + t * 2);
                        mma_bf(acc[mt][nt], ah[mt], bl4 + t * 2);
                    }
                }
            }
        }
    }

    // ---- epilogue ----
#pragma unroll
    for (int mt = 0; mt < 2; ++mt) {
        int r0 = m0 + wm * 32 + mt * 16 + (lane >> 2);
        int r1 = r0 + 8;
#pragma unroll
        for (int nt = 0; nt < 8; ++nt) {
            int col = n0 + wn * 64 + nt * 8 + ((lane & 3) << 1);
            float2 bv = *(const float2*)&bias[col];
            float2 v0 = { acc[mt][nt][0] + bv.x, acc[mt][nt][1] + bv.y };
            float2 v1 = { acc[mt][nt][2] + bv.x, acc[mt][nt][3] + bv.y };
            if (mode == 0) {
                int h_ = col >> 6, hd = col & 63;
                int b0 = r0 >> 11, s0 = r0 & 2047;
                int b1 = r1 >> 11, s1 = r1 & 2047;
                *(float2*)&C[((size_t)(b0 * HH + h_) * SS + s0) * HD + hd] = v0;
                *(float2*)&C[((size_t)(b1 * HH + h_) * SS + s1) * HD + hd] = v1;
            } else {
                *(float2*)&C[(size_t)r0 * DD + col] = v0;
                *(float2*)&C[(size_t)r1 * DD + col] = v1;
            }
        }
    }
}

// ===========================================================================
// Flash attention via mma.sync bf16 3-term compensation.
// Block = (b,h) x 128 q-rows; 8 warps x 16 q-rows each. K/V tiles of 64 keys.
// Q frags persistent in registers (pre-scaled by 1/8). S in C-frags ->
// quad-shfl softmax -> P packed to A-frags in regs -> PV with ldmatrix.trans.
// ===========================================================================
#define QHI 0
#define QLO 16384
#define KHI 0
#define KLO 8192
#define VHI 16384
#define VLO 24576

__global__ __launch_bounds__(256) void attn_mma()
{
    __shared__ char sh[32768];
    const uint32_t shb = smem_u32(sh);
    const int tid  = threadIdx.x;
    const int lane = tid & 31;
    const int wid  = tid >> 5;
    const int qt   = blockIdx.x;
    const int bh   = blockIdx.y;
    const int q0   = qt * 128;

    const float* qp = g_q + (size_t)bh * SS * HD;
    const float* kp = g_k + (size_t)bh * SS * HD;
    const float* vp = g_v + (size_t)bh * SS * HD;

    // ---- stage Q (scaled by 1/8), split hi/lo into smem ----
    {
        int row = tid >> 1;
        int c0  = (tid & 1) * 32;
        float f[32];
#pragma unroll
        for (int i = 0; i < 8; ++i)
            *(float4*)&f[i * 4] = *(const float4*)&qp[(size_t)(q0 + row) * HD + c0 + i * 4];
#pragma unroll
        for (int i = 0; i < 32; ++i) f[i] *= 0.125f;
#pragma unroll
        for (int gi = 0; gi < 4; ++gi) {
            int g = (tid & 1) * 4 + gi;
            uint32_t off = (uint32_t)row * 128 + (((uint32_t)(g ^ (row & 7))) << 4);
            const float* ff = f + gi * 8;
            uint4 h4, l4;
            h4.x = packhi(ff[0], ff[1]); h4.y = packhi(ff[2], ff[3]);
            h4.z = packhi(ff[4], ff[5]); h4.w = packhi(ff[6], ff[7]);
            l4.x = packlo(ff[0], ff[1]); l4.y = packlo(ff[2], ff[3]);
            l4.z = packlo(ff[4], ff[5]); l4.w = packlo(ff[6], ff[7]);
            *(uint4*)(sh + QHI + off) = h4;
            *(uint4*)(sh + QLO + off) = l4;
        }
    }
    __syncthreads();

    // ---- Q fragments to registers (4 k-steps over d=64) ----
    uint32_t qh[4][4], ql[4][4];
#pragma unroll
    for (int ks = 0; ks < 4; ++ks) {
        int r = wid * 16 + (lane & 15);
        int g = ks * 2 + (lane >> 4);
        uint32_t off = (uint32_t)r * 128 + (((uint32_t)(g ^ (r & 7))) << 4);
        ldsm4(qh[ks], shb + QHI + off);
        ldsm4(ql[ks], shb + QLO + off);
    }

    float o[8][4];
#pragma unroll
    for (int nt = 0; nt < 8; ++nt)
#pragma unroll
        for (int e = 0; e < 4; ++e) o[nt][e] = 0.0f;
    float m0r = -1e30f, m1r = -1e30f, l0r = 0.0f, l1r = 0.0f;

    const int frow = tid >> 2;           // 0..63 key row for fills
    const int fc   = (tid & 3) * 16;
    float4 pk[4], pv[4];
#pragma unroll
    for (int i = 0; i < 4; ++i) {
        pk[i] = *(const float4*)&kp[(size_t)frow * HD + fc + i * 4];
        pv[i] = *(const float4*)&vp[(size_t)frow * HD + fc + i * 4];
    }

    const int ktmax = 2 * qt + 2;
    const int warp_last_row = q0 + wid * 16 + 15;

    for (int kt = 0; kt < ktmax; ++kt) {
        __syncthreads();
        // ---- store K/V tiles (split hi/lo) ----
#pragma unroll
        for (int gi = 0; gi < 2; ++gi) {
            int g = (tid & 3) * 2 + gi;
            uint32_t off = (uint32_t)frow * 128 + (((uint32_t)(g ^ (frow & 7))) << 4);
            const float* fk = (const float*)&pk[gi * 2];
            const float* fv = (const float*)&pv[gi * 2];
            uint4 h4, l4;
            h4.x = packhi(fk[0], fk[1]); h4.y = packhi(fk[2], fk[3]);
            h4.z = packhi(fk[4], fk[5]); h4.w = packhi(fk[6], fk[7]);
            l4.x = packlo(fk[0], fk[1]); l4.y = packlo(fk[2], fk[3]);
            l4.z = packlo(fk[4], fk[5]); l4.w = packlo(fk[6], fk[7]);
            *(uint4*)(sh + KHI + off) = h4;
            *(uint4*)(sh + KLO + off) = l4;
            h4.x = packhi(fv[0], fv[1]); h4.y = packhi(fv[2], fv[3]);
            h4.z = packhi(fv[4], fv[5]); h4.w = packhi(fv[6], fv[7]);
            l4.x = packlo(fv[0], fv[1]); l4.y = packlo(fv[2], fv[3]);
            l4.z = packlo(fv[4], fv[5]); l4.w = packlo(fv[6], fv[7]);
            *(uint4*)(sh + VHI + off) = h4;
            *(uint4*)(sh + VLO + off) = l4;
        }
        __syncthreads();

        // ---- prefetch next K/V tile ----
        if (kt + 1 < ktmax) {
            size_t base = (size_t)((kt + 1) * 64 + frow) * HD + fc;
#pragma unroll
            for (int i = 0; i < 4; ++i) {
                pk[i] = *(const float4*)&kp[base + i * 4];
                pv[i] = *(const float4*)&vp[base + i * 4];
            }
        }

        const int k0g = kt * 64;
        if (k0g <= warp_last_row) {      // skip fully-masked tiles for this warp
            // ---- S = Q K^T (compensated) ----
            float s[8][4];
#pragma unroll
            for (int nt = 0; nt < 8; ++nt)
#pragma unroll
                for (int e = 0; e < 4; ++e) s[nt][e] = 0.0f;

#pragma unroll
            for (int ks = 0; ks < 4; ++ks) {
#pragma unroll
                for (int np = 0; np < 4; ++np) {
                    int r = np * 16 + ((lane >> 4) << 3) + (lane & 7);
                    int g = ks * 2 + ((lane >> 3) & 1);
                    uint32_t off = (uint32_t)r * 128 + (((uint32_t)(g ^ (r & 7))) << 4);
                    uint32_t kh4[4], kl4[4];
                    ldsm4(kh4, shb + KHI + off);
                    ldsm4(kl4, shb + KLO + off);
#pragma unroll
                    for (int t = 0; t < 2; ++t) {
                        int nt = np * 2 + t;
                        mma_bf(s[nt], qh[ks], kh4 + t * 2);
                        mma_bf(s[nt], ql[ks], kh4 + t * 2);
                        mma_bf(s[nt], qh[ks], kl4 + t * 2);
                    }
                }
            }

            const int r0g = q0 + wid * 16 + (lane >> 2);
            const int r1g = r0g + 8;
            if (k0g + 63 > r0g) {        // causal mask on diagonal tiles
#pragma unroll
                for (int nt = 0; nt < 8; ++nt)
#pragma unroll
                    for (int e = 0; e < 2; ++e) {
                        int col = k0g + nt * 8 + ((lane & 3) << 1) + e;
                        if (col > r0g) s[nt][e]     = -1e30f;
                        if (col > r1g) s[nt][2 + e] = -1e30f;
                    }
            }

            // ---- online softmax (rows r0g / r1g; quad = lanes sharing a row) ----
            float mx0 = -1e30f, mx1 = -1e30f;
#pragma unroll
            for (int nt = 0; nt < 8; ++nt) {
                mx0 = fmaxf(mx0, fmaxf(s[nt][0], s[nt][1]));
                mx1 = fmaxf(mx1, fmaxf(s[nt][2], s[nt][3]));
            }
            mx0 = fmaxf(mx0, __shfl_xor_sync(0xffffffffu, mx0, 1));
            mx0 = fmaxf(mx0, __shfl_xor_sync(0xffffffffu, mx0, 2));
            mx1 = fmaxf(mx1, __shfl_xor_sync(0xffffffffu, mx1, 1));
            mx1 = fmaxf(mx1, __shfl_xor_sync(0xffffffffu, mx1, 2));
            float mn0 = fmaxf(m0r, mx0), mn1 = fmaxf(m1r, mx1);
            float a0 = __expf(m0r - mn0), a1 = __expf(m1r - mn1);
            m0r = mn0; m1r = mn1;

            float sum0 = 0.0f, sum1 = 0.0f;
#pragma unroll
            for (int nt = 0; nt < 8; ++nt) {
                s[nt][0] = __expf(s[nt][0] - mn0); sum0 += s[nt][0];
                s[nt][1] = __expf(s[nt][1] - mn0); sum0 += s[nt][1];
                s[nt][2] = __expf(s[nt][2] - mn1); sum1 += s[nt][2];
                s[nt][3] = __expf(s[nt][3] - mn1); sum1 += s[nt][3];
            }
            sum0 += __shfl_xor_sync(0xffffffffu, sum0, 1);
            sum0 += __shfl_xor_sync(0xffffffffu, sum0, 2);
            sum1 += __shfl_xor_sync(0xffffffffu, sum1, 1);
            sum1 += __shfl_xor_sync(0xffffffffu, sum1, 2);
            l0r = l0r * a0 + sum0;
            l1r = l1r * a1 + sum1;
#pragma unroll
            for (int nt = 0; nt < 8; ++nt) {
                o[nt][0] *= a0; o[nt][1] *= a0;
                o[nt][2] *= a1; o[nt][3] *= a1;
            }

            // ---- O += P V (compensated); pack P frags per k-step ----
#pragma unroll
            for (int j = 0; j < 4; ++j) {
                uint32_t ph[4], plo[4];
#pragma unroll
                for (int t = 0; t < 2; ++t) {
                    int nt = j * 2 + t;
                    ph[t * 2 + 0]  = packhi(s[nt][0], s[nt][1]);
                    ph[t * 2 + 1]  = packhi(s[nt][2], s[nt][3]);
                    plo[t * 2 + 0] = packlo(s[nt][0], s[nt][1]);
                    plo[t * 2 + 1] = packlo(s[nt][2], s[nt][3]);
                }
#pragma unroll
                for (int np = 0; np < 4; ++np) {
                    int r = j * 16 + (lane & 15);
                    int g = np * 2 + (lane >> 4);
                    uint32_t off = (uint32_t)r * 128 + (((uint32_t)(g ^ (r & 7))) << 4);
                    uint32_t vh4[4], vl4[4];
                    ldsm4t(vh4, shb + VHI + off);
                    ldsm4t(vl4, shb + VLO + off);
#pragma unroll
                    for (int t = 0; t < 2; ++t) {
                        int nt = np * 2 + t;
                        mma_bf(o[nt], ph,  vh4 + t * 2);
                        mma_bf(o[nt], plo, vh4 + t * 2);
                        mma_bf(o[nt], ph,  vl4 + t * 2);
                    }
                }
            }
        }
    }

    // ---- normalize and write [B,S,D] ----
    const float inv0 = 1.0f / l0r;
    const float inv1 = 1.0f / l1r;
    const int b  = bh >> 4;
    const int h_ = bh & 15;
    const int r0 = q0 + wid * 16 + (lane >> 2);
    size_t base0 = ((size_t)b * SS + r0) * DD + h_ * 64;
    size_t base1 = base0 + (size_t)8 * DD;
#pragma unroll
    for (int nt = 0; nt < 8; ++nt) {
        int col = nt * 8 + ((lane & 3) << 1);
        float2 v0 = { o[nt][0] * inv0, o[nt][1] * inv0 };
        float2 v1 = { o[nt][2] * inv1, o[nt][3] * inv1 };
        *(float2*)&g_attn[base0 + col] = v0;
        *(float2*)&g_attn[base1 + col] = v1;
    }
}

// ---------------------------------------------------------------------------
extern "C" void kernel_launch(void* const* d_in, const int* in_sizes, int n_in,
                              void* d_out, int out_size)
{
    const float* h  = (const float*)d_in[0];
    const float* Wq = (const float*)d_in[1];
    const float* bq = (const float*)d_in[2];
    const float* Wk = (const float*)d_in[3];
    const float* bk = (const float*)d_in[4];
    const float* Wv = (const float*)d_in[5];
    const float* bv = (const float*)d_in[6];
    const float* Wo = (const float*)d_in[7];
    const float* bo = (const float*)d_in[8];
    float* out = (float*)d_out;

    float *dq, *dk, *dv, *da;
    cudaGetSymbolAddress((void**)&dq, g_q);
    cudaGetSymbolAddress((void**)&dk, g_k);
    cudaGetSymbolAddress((void**)&dv, g_v);
    cudaGetSymbolAddress((void**)&da, g_attn);

    dim3 ggrid(DD / 128, (BB * SS) / 128);   // (8, 32)

    gemm_mma<<<ggrid, 256>>>(h, Wq, bq, dq, 0);
    gemm_mma<<<ggrid, 256>>>(h, Wk, bk, dk, 0);
    gemm_mma<<<ggrid, 256>>>(h, Wv, bv, dv, 0);

    attn_mma<<<dim3(SS / 128, BB * HH), 256>>>();

    gemm_mma<<<ggrid, 256>>>(da, Wo, bo, out, 1);
}

// round 10
// speedup vs baseline: 1.0566x; 1.0566x over previous
#include <cuda_runtime.h>
#include <cuda_bf16.h>
#include <cstdint>
#include <math.h>

#define BB 2
#define SS 2048
#define DD 1024
#define HH 16
#define HD 64
#define QSCALE 0.18033688011112042f   /* 0.125 * log2(e) */

// ---------------------------------------------------------------------------
// Persistent split-bf16 scratch (hi = bf16-truncated fp32, lo = bf16(x-hi))
// ---------------------------------------------------------------------------
__device__ __nv_bfloat16 s_h_hi[BB*SS*DD],    s_h_lo[BB*SS*DD];
__device__ __nv_bfloat16 s_w_hi[4*DD*DD],     s_w_lo[4*DD*DD];
__device__ __nv_bfloat16 s_q_hi[BB*HH*SS*HD], s_q_lo[BB*HH*SS*HD];
__device__ __nv_bfloat16 s_k_hi[BB*HH*SS*HD], s_k_lo[BB*HH*SS*HD];
__device__ __nv_bfloat16 s_v_hi[BB*HH*SS*HD], s_v_lo[BB*HH*SS*HD];
__device__ __nv_bfloat16 s_a_hi[BB*SS*DD],    s_a_lo[BB*SS*DD];

// ===========================================================================
// Helpers
// ===========================================================================
__device__ __forceinline__ uint32_t smem_u32(const void* p) {
    uint32_t a;
    asm("{ .reg .u64 t; cvta.to.shared.u64 t, %1; cvt.u32.u64 %0, t; }"
        : "=r"(a) : "l"(p));
    return a;
}
__device__ __forceinline__ void ldsm4(uint32_t* r, uint32_t a) {
    asm volatile("ldmatrix.sync.aligned.m8n8.x4.shared.b16 {%0,%1,%2,%3}, [%4];"
                 : "=r"(r[0]), "=r"(r[1]), "=r"(r[2]), "=r"(r[3]) : "r"(a));
}
__device__ __forceinline__ void ldsm4t(uint32_t* r, uint32_t a) {
    asm volatile("ldmatrix.sync.aligned.m8n8.x4.trans.shared.b16 {%0,%1,%2,%3}, [%4];"
                 : "=r"(r[0]), "=r"(r[1]), "=r"(r[2]), "=r"(r[3]) : "r"(a));
}
__device__ __forceinline__ void mma_bf(float* d, const uint32_t* a, const uint32_t* b) {
    asm volatile("mma.sync.aligned.m16n8k16.row.col.f32.bf16.bf16.f32 "
                 "{%0,%1,%2,%3}, {%4,%5,%6,%7}, {%8,%9}, {%0,%1,%2,%3};"
                 : "+f"(d[0]), "+f"(d[1]), "+f"(d[2]), "+f"(d[3])
                 : "r"(a[0]), "r"(a[1]), "r"(a[2]), "r"(a[3]),
                   "r"(b[0]), "r"(b[1]));
}
__device__ __forceinline__ uint32_t packhi(float x, float y) {
    uint32_t r;
    asm("prmt.b32 %0, %1, %2, 0x7632;"
        : "=r"(r) : "r"(__float_as_uint(x)), "r"(__float_as_uint(y)));
    return r;
}
__device__ __forceinline__ uint32_t packlo(float x, float y) {
    float lx = x - __uint_as_float(__float_as_uint(x) & 0xFFFF0000u);
    float ly = y - __uint_as_float(__float_as_uint(y) & 0xFFFF0000u);
    uint32_t r;
    asm("cvt.rn.bf16x2.f32 %0, %1, %2;" : "=r"(r) : "f"(ly), "f"(lx));
    return r;
}
__device__ __forceinline__ void cpa16(uint32_t s, const void* g) {
    asm volatile("cp.async.cg.shared.global [%0], [%1], 16;"
                 :: "r"(s), "l"(g) : "memory");
}
#define CP_COMMIT() asm volatile("cp.async.commit_group;" ::: "memory")
#define CP_WAIT(n)  asm volatile("cp.async.wait_group %0;" :: "n"(n) : "memory")

// ===========================================================================
// Split fp32 -> bf16 hi/lo (one-time convert pass)
// ===========================================================================
__global__ __launch_bounds__(256) void split_fp32(const float* __restrict__ src,
                                                  __nv_bfloat16* __restrict__ hi,
                                                  __nv_bfloat16* __restrict__ lo,
                                                  int n4)
{
    int i = blockIdx.x * blockDim.x + threadIdx.x;
    if (i >= n4) return;
    float4 v = ((const float4*)src)[i];
    uint2 h4, l4;
    h4.x = packhi(v.x, v.y); h4.y = packhi(v.z, v.w);
    l4.x = packlo(v.x, v.y); l4.y = packlo(v.z, v.w);
    ((uint2*)hi)[i] = h4;
    ((uint2*)lo)[i] = l4;
}

// ===========================================================================
// Split-bf16 NT GEMM: C[m,n] = sum_k A[m,k]*W[n,k] + bias[n]  (3-term comp.)
// Block 128x128x32; 8 warps 4m x 2n; cp.async 2-stage double buffer.
// mode 0: epilogue scales and writes split bf16, head-major [B,H,S,HD]
//         (blockIdx.z picks the q/k/v stream; q gets QSCALE folded in)
// mode 1: fp32 plain [row,col] store to fout.
// ===========================================================================
#define G_AH 0
#define G_AL 8192
#define G_BH 16384
#define G_BL 24576
#define G_STAGE 32768
#define G_SMEM  65536

__global__ __launch_bounds__(256) void gemm_bf(
    const __nv_bfloat16* __restrict__ Ahi, const __nv_bfloat16* __restrict__ Alo,
    const __nv_bfloat16* __restrict__ Whi, const __nv_bfloat16* __restrict__ Wlo,
    const float* __restrict__ b0p, const float* __restrict__ b1p,
    const float* __restrict__ b2p,
    __nv_bfloat16* d0h, __nv_bfloat16* d0l,
    __nv_bfloat16* d1h, __nv_bfloat16* d1l,
    __nv_bfloat16* d2h, __nv_bfloat16* d2l,
    float* fout, int mode)
{
    extern __shared__ char sh[];
    const uint32_t shb = smem_u32(sh);
    const int tid  = threadIdx.x;
    const int lane = tid & 31;
    const int wid  = tid >> 5;
    const int wm   = wid & 3;
    const int wn   = wid >> 2;
    const int m0   = blockIdx.y * 128;
    const int n0   = blockIdx.x * 128;
    const int z    = blockIdx.z;

    const __nv_bfloat16* Wh = Whi + (size_t)z * DD * DD;
    const __nv_bfloat16* Wl = Wlo + (size_t)z * DD * DD;
    const float* bias = (z == 0) ? b0p : (z == 1) ? b1p : b2p;

    const int frow  = tid >> 1;          // 0..127
    const int cbase = (tid & 1) * 2;     // chunk base within 64B row

    float acc[2][8][4];
#pragma unroll
    for (int mt = 0; mt < 2; ++mt)
#pragma unroll
        for (int nt = 0; nt < 8; ++nt)
#pragma unroll
            for (int e = 0; e < 4; ++e) acc[mt][nt][e] = 0.0f;

    // fill one stage with k-block kb
    auto fill = [&](int st, int kb) {
        uint32_t sb = shb + st * G_STAGE;
        size_t ga = (size_t)(m0 + frow) * DD + kb * 32;
        size_t gb = (size_t)(n0 + frow) * DD + kb * 32;
#pragma unroll
        for (int ci = 0; ci < 2; ++ci) {
            int c = cbase + ci;
            uint32_t off = (uint32_t)frow * 64 + (((uint32_t)(c ^ (frow & 3))) << 4);
            cpa16(sb + G_AH + off, Ahi + ga + c * 8);
            cpa16(sb + G_AL + off, Alo + ga + c * 8);
            cpa16(sb + G_BH + off, Wh + gb + c * 8);
            cpa16(sb + G_BL + off, Wl + gb + c * 8);
        }
    };

    fill(0, 0);
    CP_COMMIT();

    const int KB = DD / 32;
    for (int kb = 0; kb < KB; ++kb) {
        const int st = kb & 1;
        if (kb + 1 < KB) { fill(st ^ 1, kb + 1); CP_COMMIT(); CP_WAIT(1); }
        else             { CP_WAIT(0); }
        __syncthreads();

        const uint32_t sb = shb + st * G_STAGE;
#pragma unroll
        for (int ks = 0; ks < 2; ++ks) {
            uint32_t ah[2][4], al[2][4];
#pragma unroll
            for (int mt = 0; mt < 2; ++mt) {
                int r = wm * 32 + mt * 16 + (lane & 15);
                int g = ks * 2 + (lane >> 4);
                uint32_t off = (uint32_t)r * 64 + (((uint32_t)(g ^ (r & 3))) << 4);
                ldsm4(ah[mt], sb + G_AH + off);
                ldsm4(al[mt], sb + G_AL + off);
            }
#pragma unroll
            for (int np = 0; np < 4; ++np) {
                int r = wn * 64 + np * 16 + ((lane >> 4) << 3) + (lane & 7);
                int g = ks * 2 + ((lane >> 3) & 1);
                uint32_t off = (uint32_t)r * 64 + (((uint32_t)(g ^ (r & 3))) << 4);
                uint32_t bh4[4], bl4[4];
                ldsm4(bh4, sb + G_BH + off);
                ldsm4(bl4, sb + G_BL + off);
#pragma unroll
                for (int t = 0; t < 2; ++t) {
                    int nt = np * 2 + t;
#pragma unroll
                    for (int mt = 0; mt < 2; ++mt) {
                        mma_bf(acc[mt][nt], ah[mt], bh4 + t * 2);
                        mma_bf(acc[mt][nt], al[mt], bh4 + t * 2);
                        mma_bf(acc[mt][nt], ah[mt], bl4 + t * 2);
                    }
                }
            }
        }
        __syncthreads();
    }

    // ---- epilogue ----
    const float scale = (mode == 0 && z == 0) ? QSCALE : 1.0f;
    __nv_bfloat16* dh = (z == 0) ? d0h : (z == 1) ? d1h : d2h;
    __nv_bfloat16* dl = (z == 0) ? d0l : (z == 1) ? d1l : d2l;

#pragma unroll
    for (int mt = 0; mt < 2; ++mt) {
        int r0 = m0 + wm * 32 + mt * 16 + (lane >> 2);
        int r1 = r0 + 8;
#pragma unroll
        for (int nt = 0; nt < 8; ++nt) {
            int col = n0 + wn * 64 + nt * 8 + ((lane & 3) << 1);
            float2 bv = *(const float2*)&bias[col];
            float v0x = (acc[mt][nt][0] + bv.x) * scale;
            float v0y = (acc[mt][nt][1] + bv.y) * scale;
            float v1x = (acc[mt][nt][2] + bv.x) * scale;
            float v1y = (acc[mt][nt][3] + bv.y) * scale;
            if (mode == 0) {
                int h_ = col >> 6, hd = col & 63;
                int b0 = r0 >> 11, ss0 = r0 & 2047;
                int b1 = r1 >> 11, ss1 = r1 & 2047;
                size_t i0 = ((size_t)(b0 * HH + h_) * SS + ss0) * HD + hd;
                size_t i1 = ((size_t)(b1 * HH + h_) * SS + ss1) * HD + hd;
                *(uint32_t*)&dh[i0] = packhi(v0x, v0y);
                *(uint32_t*)&dl[i0] = packlo(v0x, v0y);
                *(uint32_t*)&dh[i1] = packhi(v1x, v1y);
                *(uint32_t*)&dl[i1] = packlo(v1x, v1y);
            } else {
                float2 o0 = { v0x, v0y }, o1 = { v1x, v1y };
                *(float2*)&fout[(size_t)r0 * DD + col] = o0;
                *(float2*)&fout[(size_t)r1 * DD + col] = o1;
            }
        }
    }
}

// ===========================================================================
// Flash attention on pre-split bf16 q/k/v; cp.async 2-stage K/V double buffer.
// Block = (b,h) x 128 q-rows; 8 warps x 16 rows. exp2f softmax (scale folded
// into Q). Output written split bf16 to s_a_hi/lo [B,S,D].
// ===========================================================================
#define A_QH 0
#define A_QL 16384
#define A_KH 0
#define A_KL 8192
#define A_VH 16384
#define A_VL 24576
#define A_STAGE 32768
#define A_SMEM  65536

__global__ __launch_bounds__(256) void attn_bf()
{
    extern __shared__ char sh[];
    const uint32_t shb = smem_u32(sh);
    const int tid  = threadIdx.x;
    const int lane = tid & 31;
    const int wid  = tid >> 5;
    const int qt   = blockIdx.x;
    const int bh   = blockIdx.y;
    const int q0   = qt * 128;

    const __nv_bfloat16* qh_g = s_q_hi + (size_t)bh * SS * HD;
    const __nv_bfloat16* ql_g = s_q_lo + (size_t)bh * SS * HD;
    const __nv_bfloat16* kh_g = s_k_hi + (size_t)bh * SS * HD;
    const __nv_bfloat16* kl_g = s_k_lo + (size_t)bh * SS * HD;
    const __nv_bfloat16* vh_g = s_v_hi + (size_t)bh * SS * HD;
    const __nv_bfloat16* vl_g = s_v_lo + (size_t)bh * SS * HD;

    // ---- stage Q (hi/lo) via cp.async, then ldsm to registers ----
    {
        int row = tid >> 1;                 // 0..127
        int cb  = (tid & 1) * 4;            // 4 chunks of the 8 per 128B row
        size_t g = (size_t)(q0 + row) * HD;
#pragma unroll
        for (int ci = 0; ci < 4; ++ci) {
            int c = cb + ci;
            uint32_t off = (uint32_t)row * 128 + (((uint32_t)(c ^ (row & 7))) << 4);
            cpa16(shb + A_QH + off, qh_g + g + c * 8);
            cpa16(shb + A_QL + off, ql_g + g + c * 8);
        }
    }
    CP_COMMIT();
    CP_WAIT(0);
    __syncthreads();

    uint32_t qh[4][4], ql[4][4];
#pragma unroll
    for (int ks = 0; ks < 4; ++ks) {
        int r = wid * 16 + (lane & 15);
        int g = ks * 2 + (lane >> 4);
        uint32_t off = (uint32_t)r * 128 + (((uint32_t)(g ^ (r & 7))) << 4);
        ldsm4(qh[ks], shb + A_QH + off);
        ldsm4(ql[ks], shb + A_QL + off);
    }
    __syncthreads();   // all warps done with Q smem before K/V refill

    float o[8][4];
#pragma unroll
    for (int nt = 0; nt < 8; ++nt)
#pragma unroll
        for (int e = 0; e < 4; ++e) o[nt][e] = 0.0f;
    float m0r = -1e30f, m1r = -1e30f, l0r = 0.0f, l1r = 0.0f;

    const int frow = tid >> 2;              // 0..63
    const int fcb  = (tid & 3) * 2;         // 2 chunks of 8 per 128B row

    auto fillkv = [&](int st, int kt) {
        uint32_t sb = shb + st * A_STAGE;
        size_t g = (size_t)(kt * 64 + frow) * HD;
#pragma unroll
        for (int ci = 0; ci < 2; ++ci) {
            int c = fcb + ci;
            uint32_t off = (uint32_t)frow * 128 + (((uint32_t)(c ^ (frow & 7))) << 4);
            cpa16(sb + A_KH + off, kh_g + g + c * 8);
            cpa16(sb + A_KL + off, kl_g + g + c * 8);
            cpa16(sb + A_VH + off, vh_g + g + c * 8);
            cpa16(sb + A_VL + off, vl_g + g + c * 8);
        }
    };

    const int ktmax = 2 * qt + 2;
    const int warp_last_row = q0 + wid * 16 + 15;

    fillkv(0, 0);
    CP_COMMIT();

    for (int kt = 0; kt < ktmax; ++kt) {
        const int st = kt & 1;
        if (kt + 1 < ktmax) { fillkv(st ^ 1, kt + 1); CP_COMMIT(); CP_WAIT(1); }
        else                { CP_WAIT(0); }
        __syncthreads();

        const int k0g = kt * 64;
        if (k0g <= warp_last_row) {
            const uint32_t sb = shb + st * A_STAGE;

            // ---- S = Q K^T (compensated; already scaled by 0.125*log2e) ----
            float s[8][4];
#pragma unroll
            for (int nt = 0; nt < 8; ++nt)
#pragma unroll
                for (int e = 0; e < 4; ++e) s[nt][e] = 0.0f;

#pragma unroll
            for (int ks = 0; ks < 4; ++ks) {
#pragma unroll
                for (int np = 0; np < 4; ++np) {
                    int r = np * 16 + ((lane >> 4) << 3) + (lane & 7);
                    int g = ks * 2 + ((lane >> 3) & 1);
                    uint32_t off = (uint32_t)r * 128 + (((uint32_t)(g ^ (r & 7))) << 4);
                    uint32_t kh4[4], kl4[4];
                    ldsm4(kh4, sb + A_KH + off);
                    ldsm4(kl4, sb + A_KL + off);
#pragma unroll
                    for (int t = 0; t < 2; ++t) {
                        int nt = np * 2 + t;
                        mma_bf(s[nt], qh[ks], kh4 + t * 2);
                        mma_bf(s[nt], ql[ks], kh4 + t * 2);
                        mma_bf(s[nt], qh[ks], kl4 + t * 2);
                    }
                }
            }

            const int r0g = q0 + wid * 16 + (lane >> 2);
            const int r1g = r0g + 8;
            if (k0g + 63 > r0g) {
#pragma unroll
                for (int nt = 0; nt < 8; ++nt)
#pragma unroll
                    for (int e = 0; e < 2; ++e) {
                        int col = k0g + nt * 8 + ((lane & 3) << 1) + e;
                        if (col > r0g) s[nt][e]     = -1e30f;
                        if (col > r1g) s[nt][2 + e] = -1e30f;
                    }
            }

            // ---- online softmax (exp2 domain) ----
            float mx0 = -1e30f, mx1 = -1e30f;
#pragma unroll
            for (int nt = 0; nt < 8; ++nt) {
                mx0 = fmaxf(mx0, fmaxf(s[nt][0], s[nt][1]));
                mx1 = fmaxf(mx1, fmaxf(s[nt][2], s[nt][3]));
            }
            mx0 = fmaxf(mx0, __shfl_xor_sync(0xffffffffu, mx0, 1));
            mx0 = fmaxf(mx0, __shfl_xor_sync(0xffffffffu, mx0, 2));
            mx1 = fmaxf(mx1, __shfl_xor_sync(0xffffffffu, mx1, 1));
            mx1 = fmaxf(mx1, __shfl_xor_sync(0xffffffffu, mx1, 2));
            float mn0 = fmaxf(m0r, mx0), mn1 = fmaxf(m1r, mx1);
            float a0 = exp2f(m0r - mn0), a1 = exp2f(m1r - mn1);
            m0r = mn0; m1r = mn1;

            float sum0 = 0.0f, sum1 = 0.0f;
#pragma unroll
            for (int nt = 0; nt < 8; ++nt) {
                s[nt][0] = exp2f(s[nt][0] - mn0); sum0 += s[nt][0];
                s[nt][1] = exp2f(s[nt][1] - mn0); sum0 += s[nt][1];
                s[nt][2] = exp2f(s[nt][2] - mn1); sum1 += s[nt][2];
                s[nt][3] = exp2f(s[nt][3] - mn1); sum1 += s[nt][3];
            }
            sum0 += __shfl_xor_sync(0xffffffffu, sum0, 1);
            sum0 += __shfl_xor_sync(0xffffffffu, sum0, 2);
            sum1 += __shfl_xor_sync(0xffffffffu, sum1, 1);
            sum1 += __shfl_xor_sync(0xffffffffu, sum1, 2);
            l0r = l0r * a0 + sum0;
            l1r = l1r * a1 + sum1;
#pragma unroll
            for (int nt = 0; nt < 8; ++nt) {
                o[nt][0] *= a0; o[nt][1] *= a0;
                o[nt][2] *= a1; o[nt][3] *= a1;
            }

            // ---- O += P V (compensated) ----
#pragma unroll
            for (int j = 0; j < 4; ++j) {
                uint32_t ph[4], plo[4];
#pragma unroll
                for (int t = 0; t < 2; ++t) {
                    int nt = j * 2 + t;
                    ph[t * 2 + 0]  = packhi(s[nt][0], s[nt][1]);
                    ph[t * 2 + 1]  = packhi(s[nt][2], s[nt][3]);
                    plo[t * 2 + 0] = packlo(s[nt][0], s[nt][1]);
                    plo[t * 2 + 1] = packlo(s[nt][2], s[nt][3]);
                }
#pragma unroll
                for (int np = 0; np < 4; ++np) {
                    int r = j * 16 + (lane & 15);
                    int g = np * 2 + (lane >> 4);
                    uint32_t off = (uint32_t)r * 128 + (((uint32_t)(g ^ (r & 7))) << 4);
                    uint32_t vh4[4], vl4[4];
                    ldsm4t(vh4, sb + A_VH + off);
                    ldsm4t(vl4, sb + A_VL + off);
#pragma unroll
                    for (int t = 0; t < 2; ++t) {
                        int nt = np * 2 + t;
                        mma_bf(o[nt], ph,  vh4 + t * 2);
                        mma_bf(o[nt], plo, vh4 + t * 2);
                        mma_bf(o[nt], ph,  vl4 + t * 2);
                    }
                }
            }
        }
        __syncthreads();
    }

    // ---- normalize and write split bf16 to [B,S,D] ----
    const float inv0 = 1.0f / l0r;
    const float inv1 = 1.0f / l1r;
    const int b  = bh >> 4;
    const int h_ = bh & 15;
    const int r0 = q0 + wid * 16 + (lane >> 2);
    size_t base0 = ((size_t)b * SS + r0) * DD + h_ * 64;
    size_t base1 = base0 + (size_t)8 * DD;
#pragma unroll
    for (int nt = 0; nt < 8; ++nt) {
        int col = nt * 8 + ((lane & 3) << 1);
        float v0x = o[nt][0] * inv0, v0y = o[nt][1] * inv0;
        float v1x = o[nt][2] * inv1, v1y = o[nt][3] * inv1;
        *(uint32_t*)&s_a_hi[base0 + col] = packhi(v0x, v0y);
        *(uint32_t*)&s_a_lo[base0 + col] = packlo(v0x, v0y);
        *(uint32_t*)&s_a_hi[base1 + col] = packhi(v1x, v1y);
        *(uint32_t*)&s_a_lo[base1 + col] = packlo(v1x, v1y);
    }
}

// ---------------------------------------------------------------------------
extern "C" void kernel_launch(void* const* d_in, const int* in_sizes, int n_in,
                              void* d_out, int out_size)
{
    const float* h  = (const float*)d_in[0];
    const float* Wq = (const float*)d_in[1];
    const float* bq = (const float*)d_in[2];
    const float* Wk = (const float*)d_in[3];
    const float* bk = (const float*)d_in[4];
    const float* Wv = (const float*)d_in[5];
    const float* bv = (const float*)d_in[6];
    const float* Wo = (const float*)d_in[7];
    const float* bo = (const float*)d_in[8];
    float* out = (float*)d_out;

    __nv_bfloat16 *hh, *hl, *wh, *wl, *qh, *qlp, *kh, *kl, *vh, *vl, *ah, *al;
    cudaGetSymbolAddress((void**)&hh,  s_h_hi);
    cudaGetSymbolAddress((void**)&hl,  s_h_lo);
    cudaGetSymbolAddress((void**)&wh,  s_w_hi);
    cudaGetSymbolAddress((void**)&wl,  s_w_lo);
    cudaGetSymbolAddress((void**)&qh,  s_q_hi);
    cudaGetSymbolAddress((void**)&qlp, s_q_lo);
    cudaGetSymbolAddress((void**)&kh,  s_k_hi);
    cudaGetSymbolAddress((void**)&kl,  s_k_lo);
    cudaGetSymbolAddress((void**)&vh,  s_v_hi);
    cudaGetSymbolAddress((void**)&vl,  s_v_lo);
    cudaGetSymbolAddress((void**)&ah,  s_a_hi);
    cudaGetSymbolAddress((void**)&al,  s_a_lo);

    cudaFuncSetAttribute(gemm_bf, cudaFuncAttributeMaxDynamicSharedMemorySize, G_SMEM);
    cudaFuncSetAttribute(attn_bf, cudaFuncAttributeMaxDynamicSharedMemorySize, A_SMEM);

    // ---- convert inputs to split bf16 ----
    const int HN4 = BB * SS * DD / 4;     // 1048576
    const int WN4 = DD * DD / 4;          // 262144
    split_fp32<<<HN4 / 256, 256>>>(h,  hh, hl, HN4);
    split_fp32<<<WN4 / 256, 256>>>(Wq, wh + 0 * DD * DD, wl + 0 * DD * DD, WN4);
    split_fp32<<<WN4 / 256, 256>>>(Wk, wh + 1 * DD * DD, wl + 1 * DD * DD, WN4);
    split_fp32<<<WN4 / 256, 256>>>(Wv, wh + 2 * DD * DD, wl + 2 * DD * DD, WN4);
    split_fp32<<<WN4 / 256, 256>>>(Wo, wh + 3 * DD * DD, wl + 3 * DD * DD, WN4);

    // ---- fused QKV projection (z selects q/k/v) ----
    dim3 qkv_grid(DD / 128, (BB * SS) / 128, 3);   // (8, 32, 3)
    gemm_bf<<<qkv_grid, 256, G_SMEM>>>(hh, hl, wh, wl,
                                       bq, bk, bv,
                                       qh, qlp, kh, kl, vh, vl,
                                       nullptr, 0);

    // ---- attention ----
    attn_bf<<<dim3(SS / 128, BB * HH), 256, A_SMEM>>>();

    // ---- output projection ----
    dim3 o_grid(DD / 128, (BB * SS) / 128, 1);
    gemm_bf<<<o_grid, 256, G_SMEM>>>(ah, al, wh + 3 * (size_t)DD * DD,
                                     wl + 3 * (size_t)DD * DD,
                                     bo, bo, bo,
                                     nullptr, nullptr, nullptr, nullptr,
                                     nullptr, nullptr,
                                     out, 1);
}

// round 11
// speedup vs baseline: 1.2022x; 1.1378x over previous
#include <cuda_runtime.h>
#include <cuda_bf16.h>
#include <cstdint>
#include <math.h>

#define BB 2
#define SS 2048
#define DD 1024
#define HH 16
#define HD 64
#define QSCALE 0.18033688011112042f   /* 0.125 * log2(e) */

// ---------------------------------------------------------------------------
// Persistent split-bf16 scratch (hi = bf16-truncated fp32, lo = bf16(x-hi))
// ---------------------------------------------------------------------------
__device__ __nv_bfloat16 s_h_hi[BB*SS*DD],    s_h_lo[BB*SS*DD];
__device__ __nv_bfloat16 s_w_hi[4*DD*DD],     s_w_lo[4*DD*DD];
__device__ __nv_bfloat16 s_q_hi[BB*HH*SS*HD], s_q_lo[BB*HH*SS*HD];
__device__ __nv_bfloat16 s_k_hi[BB*HH*SS*HD], s_k_lo[BB*HH*SS*HD];
__device__ __nv_bfloat16 s_v_hi[BB*HH*SS*HD], s_v_lo[BB*HH*SS*HD];
__device__ __nv_bfloat16 s_a_hi[BB*SS*DD],    s_a_lo[BB*SS*DD];

// ===========================================================================
// Helpers
// ===========================================================================
__device__ __forceinline__ uint32_t smem_u32(const void* p) {
    uint32_t a;
    asm("{ .reg .u64 t; cvta.to.shared.u64 t, %1; cvt.u32.u64 %0, t; }"
        : "=r"(a) : "l"(p));
    return a;
}
__device__ __forceinline__ void ldsm4(uint32_t* r, uint32_t a) {
    asm volatile("ldmatrix.sync.aligned.m8n8.x4.shared.b16 {%0,%1,%2,%3}, [%4];"
                 : "=r"(r[0]), "=r"(r[1]), "=r"(r[2]), "=r"(r[3]) : "r"(a));
}
__device__ __forceinline__ void ldsm4t(uint32_t* r, uint32_t a) {
    asm volatile("ldmatrix.sync.aligned.m8n8.x4.trans.shared.b16 {%0,%1,%2,%3}, [%4];"
                 : "=r"(r[0]), "=r"(r[1]), "=r"(r[2]), "=r"(r[3]) : "r"(a));
}
__device__ __forceinline__ void mma_bf(float* d, const uint32_t* a, const uint32_t* b) {
    asm volatile("mma.sync.aligned.m16n8k16.row.col.f32.bf16.bf16.f32 "
                 "{%0,%1,%2,%3}, {%4,%5,%6,%7}, {%8,%9}, {%0,%1,%2,%3};"
                 : "+f"(d[0]), "+f"(d[1]), "+f"(d[2]), "+f"(d[3])
                 : "r"(a[0]), "r"(a[1]), "r"(a[2]), "r"(a[3]),
                   "r"(b[0]), "r"(b[1]));
}
__device__ __forceinline__ uint32_t packhi(float x, float y) {
    uint32_t r;
    asm("prmt.b32 %0, %1, %2, 0x7632;"
        : "=r"(r) : "r"(__float_as_uint(x)), "r"(__float_as_uint(y)));
    return r;
}
__device__ __forceinline__ uint32_t packlo(float x, float y) {
    float lx = x - __uint_as_float(__float_as_uint(x) & 0xFFFF0000u);
    float ly = y - __uint_as_float(__float_as_uint(y) & 0xFFFF0000u);
    uint32_t r;
    asm("cvt.rn.bf16x2.f32 %0, %1, %2;" : "=r"(r) : "f"(ly), "f"(lx));
    return r;
}
__device__ __forceinline__ void cpa16(uint32_t s, const void* g) {
    asm volatile("cp.async.cg.shared.global [%0], [%1], 16;"
                 :: "r"(s), "l"(g) : "memory");
}
#define CP_COMMIT() asm volatile("cp.async.commit_group;" ::: "memory")
#define CP_WAIT(n)  asm volatile("cp.async.wait_group %0;" :: "n"(n) : "memory")

// ===========================================================================
// Merged split pass: h + 4 weights -> bf16 hi/lo in ONE launch
// ===========================================================================
#define HN4 (BB * SS * DD / 4)
#define WN4 (DD * DD / 4)

__global__ __launch_bounds__(256) void split_all(
    const float* __restrict__ h,
    const float* __restrict__ Wq, const float* __restrict__ Wk,
    const float* __restrict__ Wv, const float* __restrict__ Wo,
    __nv_bfloat16* __restrict__ hh, __nv_bfloat16* __restrict__ hl,
    __nv_bfloat16* __restrict__ wh, __nv_bfloat16* __restrict__ wl)
{
    int i = blockIdx.x * blockDim.x + threadIdx.x;
    const float* src;
    __nv_bfloat16 *dh, *dl;
    int j;
    if (i < HN4) {
        src = h; dh = hh; dl = hl; j = i;
    } else {
        int w = (i - HN4) >> 18;            // / WN4 (=262144)
        j = (i - HN4) & (WN4 - 1);
        src = (w == 0) ? Wq : (w == 1) ? Wk : (w == 2) ? Wv : Wo;
        dh = wh + (size_t)w * DD * DD / 4 * 4;
        dl = wl + (size_t)w * DD * DD / 4 * 4;
    }
    float4 v = ((const float4*)src)[j];
    uint2 h4, l4;
    h4.x = packhi(v.x, v.y); h4.y = packhi(v.z, v.w);
    l4.x = packlo(v.x, v.y); l4.y = packlo(v.z, v.w);
    ((uint2*)dh)[j] = h4;
    ((uint2*)dl)[j] = l4;
}

// ===========================================================================
// Split-bf16 NT GEMM (3-term compensation), 128x128x32 tile, 8 warps 4m x 2n.
// 3-stage cp.async pipeline, ONE __syncthreads per k-slab, 2 CTAs/SM.
// MMA issued in 3 passes (hh, lh, hl) for accumulator-reuse distance 4.
// ===========================================================================
#define G_AH 0
#define G_AL 8192
#define G_BH 16384
#define G_BL 24576
#define G_STAGE 32768
#define G_SMEM  (3 * G_STAGE)          /* 98304 */

__global__ __launch_bounds__(256, 2) void gemm_bf(
    const __nv_bfloat16* __restrict__ Ahi, const __nv_bfloat16* __restrict__ Alo,
    const __nv_bfloat16* __restrict__ Whi, const __nv_bfloat16* __restrict__ Wlo,
    const float* __restrict__ b0p, const float* __restrict__ b1p,
    const float* __restrict__ b2p,
    __nv_bfloat16* d0h, __nv_bfloat16* d0l,
    __nv_bfloat16* d1h, __nv_bfloat16* d1l,
    __nv_bfloat16* d2h, __nv_bfloat16* d2l,
    float* fout, int mode)
{
    extern __shared__ char sh[];
    const uint32_t shb = smem_u32(sh);
    const int tid  = threadIdx.x;
    const int lane = tid & 31;
    const int wid  = tid >> 5;
    const int wm   = wid & 3;
    const int wn   = wid >> 2;
    const int m0   = blockIdx.y * 128;
    const int n0   = blockIdx.x * 128;
    const int z    = blockIdx.z;

    const __nv_bfloat16* Wh = Whi + (size_t)z * DD * DD;
    const __nv_bfloat16* Wl = Wlo + (size_t)z * DD * DD;
    const float* bias = (z == 0) ? b0p : (z == 1) ? b1p : b2p;

    const int frow  = tid >> 1;
    const int cbase = (tid & 1) * 2;

    float acc[2][8][4];
#pragma unroll
    for (int mt = 0; mt < 2; ++mt)
#pragma unroll
        for (int nt = 0; nt < 8; ++nt)
#pragma unroll
            for (int e = 0; e < 4; ++e) acc[mt][nt][e] = 0.0f;

    auto fill = [&](int st, int kb) {
        uint32_t sb = shb + st * G_STAGE;
        size_t ga = (size_t)(m0 + frow) * DD + kb * 32;
        size_t gb = (size_t)(n0 + frow) * DD + kb * 32;
#pragma unroll
        for (int ci = 0; ci < 2; ++ci) {
            int c = cbase + ci;
            uint32_t off = (uint32_t)frow * 64 + (((uint32_t)(c ^ (frow & 3))) << 4);
            cpa16(sb + G_AH + off, Ahi + ga + c * 8);
            cpa16(sb + G_AL + off, Alo + ga + c * 8);
            cpa16(sb + G_BH + off, Wh + gb + c * 8);
            cpa16(sb + G_BL + off, Wl + gb + c * 8);
        }
    };

    fill(0, 0); CP_COMMIT();
    fill(1, 1); CP_COMMIT();

    const int KB = DD / 32;
    int st = 0;
    for (int kb = 0; kb < KB; ++kb) {
        if (kb + 2 < KB) CP_WAIT(1); else CP_WAIT(0);
        __syncthreads();
        if (kb + 2 < KB) { fill((st + 2) % 3, kb + 2); CP_COMMIT(); }

        const uint32_t sb = shb + st * G_STAGE;
#pragma unroll
        for (int ks = 0; ks < 2; ++ks) {
            uint32_t ah[2][4], al[2][4];
#pragma unroll
            for (int mt = 0; mt < 2; ++mt) {
                int r = wm * 32 + mt * 16 + (lane & 15);
                int g = ks * 2 + (lane >> 4);
                uint32_t off = (uint32_t)r * 64 + (((uint32_t)(g ^ (r & 3))) << 4);
                ldsm4(ah[mt], sb + G_AH + off);
                ldsm4(al[mt], sb + G_AL + off);
            }
#pragma unroll
            for (int np = 0; np < 4; ++np) {
                int r = wn * 64 + np * 16 + ((lane >> 4) << 3) + (lane & 7);
                int g = ks * 2 + ((lane >> 3) & 1);
                uint32_t off = (uint32_t)r * 64 + (((uint32_t)(g ^ (r & 3))) << 4);
                uint32_t bh4[4], bl4[4];
                ldsm4(bh4, sb + G_BH + off);
                ldsm4(bl4, sb + G_BL + off);
                // pass 1: hh
#pragma unroll
                for (int mt = 0; mt < 2; ++mt)
#pragma unroll
                    for (int t = 0; t < 2; ++t)
                        mma_bf(acc[mt][np * 2 + t], ah[mt], bh4 + t * 2);
                // pass 2: lh
#pragma unroll
                for (int mt = 0; mt < 2; ++mt)
#pragma unroll
                    for (int t = 0; t < 2; ++t)
                        mma_bf(acc[mt][np * 2 + t], al[mt], bh4 + t * 2);
                // pass 3: hl
#pragma unroll
                for (int mt = 0; mt < 2; ++mt)
#pragma unroll
                    for (int t = 0; t < 2; ++t)
                        mma_bf(acc[mt][np * 2 + t], ah[mt], bl4 + t * 2);
            }
        }
        st = (st + 1) % 3;
    }

    // ---- epilogue ----
    const float scale = (mode == 0 && z == 0) ? QSCALE : 1.0f;
    __nv_bfloat16* dh = (z == 0) ? d0h : (z == 1) ? d1h : d2h;
    __nv_bfloat16* dl = (z == 0) ? d0l : (z == 1) ? d1l : d2l;

#pragma unroll
    for (int mt = 0; mt < 2; ++mt) {
        int r0 = m0 + wm * 32 + mt * 16 + (lane >> 2);
        int r1 = r0 + 8;
#pragma unroll
        for (int nt = 0; nt < 8; ++nt) {
            int col = n0 + wn * 64 + nt * 8 + ((lane & 3) << 1);
            float2 bv = *(const float2*)&bias[col];
            float v0x = (acc[mt][nt][0] + bv.x) * scale;
            float v0y = (acc[mt][nt][1] + bv.y) * scale;
            float v1x = (acc[mt][nt][2] + bv.x) * scale;
            float v1y = (acc[mt][nt][3] + bv.y) * scale;
            if (mode == 0) {
                int h_ = col >> 6, hd = col & 63;
                int b0 = r0 >> 11, ss0 = r0 & 2047;
                int b1 = r1 >> 11, ss1 = r1 & 2047;
                size_t i0 = ((size_t)(b0 * HH + h_) * SS + ss0) * HD + hd;
                size_t i1 = ((size_t)(b1 * HH + h_) * SS + ss1) * HD + hd;
                *(uint32_t*)&dh[i0] = packhi(v0x, v0y);
                *(uint32_t*)&dl[i0] = packlo(v0x, v0y);
                *(uint32_t*)&dh[i1] = packhi(v1x, v1y);
                *(uint32_t*)&dl[i1] = packlo(v1x, v1y);
            } else {
                float2 o0 = { v0x, v0y }, o1 = { v1x, v1y };
                *(float2*)&fout[(size_t)r0 * DD + col] = o0;
                *(float2*)&fout[(size_t)r1 * DD + col] = o1;
            }
        }
    }
}

// ===========================================================================
// Flash attention on pre-split bf16; 3-stage K/V pipeline (stages AFTER Q
// region), ONE sync per tile, batched ldsm + 3-pass compensated MMA.
// ===========================================================================
#define A_QH 0
#define A_QL 16384
#define A_KH 0
#define A_KL 8192
#define A_VH 16384
#define A_VL 24576
#define A_STB   32768                  /* stage region base (after Q) */
#define A_STAGE 32768
#define A_SMEM  (A_STB + 3 * A_STAGE)  /* 131072 */

__global__ __launch_bounds__(256) void attn_bf()
{
    extern __shared__ char sh[];
    const uint32_t shb = smem_u32(sh);
    const int tid  = threadIdx.x;
    const int lane = tid & 31;
    const int wid  = tid >> 5;
    const int qt   = blockIdx.x;
    const int bh   = blockIdx.y;
    const int q0   = qt * 128;

    const __nv_bfloat16* qh_g = s_q_hi + (size_t)bh * SS * HD;
    const __nv_bfloat16* ql_g = s_q_lo + (size_t)bh * SS * HD;
    const __nv_bfloat16* kh_g = s_k_hi + (size_t)bh * SS * HD;
    const __nv_bfloat16* kl_g = s_k_lo + (size_t)bh * SS * HD;
    const __nv_bfloat16* vh_g = s_v_hi + (size_t)bh * SS * HD;
    const __nv_bfloat16* vl_g = s_v_lo + (size_t)bh * SS * HD;

    // ---- stage Q (hi/lo) via cp.async, then ldsm to registers ----
    {
        int row = tid >> 1;
        int cb  = (tid & 1) * 4;
        size_t g = (size_t)(q0 + row) * HD;
#pragma unroll
        for (int ci = 0; ci < 4; ++ci) {
            int c = cb + ci;
            uint32_t off = (uint32_t)row * 128 + (((uint32_t)(c ^ (row & 7))) << 4);
            cpa16(shb + A_QH + off, qh_g + g + c * 8);
            cpa16(shb + A_QL + off, ql_g + g + c * 8);
        }
    }
    CP_COMMIT();
    CP_WAIT(0);
    __syncthreads();

    uint32_t qh[4][4], ql[4][4];
#pragma unroll
    for (int ks = 0; ks < 4; ++ks) {
        int r = wid * 16 + (lane & 15);
        int g = ks * 2 + (lane >> 4);
        uint32_t off = (uint32_t)r * 128 + (((uint32_t)(g ^ (r & 7))) << 4);
        ldsm4(qh[ks], shb + A_QH + off);
        ldsm4(ql[ks], shb + A_QL + off);
    }

    float o[8][4];
#pragma unroll
    for (int nt = 0; nt < 8; ++nt)
#pragma unroll
        for (int e = 0; e < 4; ++e) o[nt][e] = 0.0f;
    float m0r = -1e30f, m1r = -1e30f, l0r = 0.0f, l1r = 0.0f;

    const int frow = tid >> 2;
    const int fcb  = (tid & 3) * 2;

    auto fillkv = [&](int st, int kt) {
        uint32_t sb = shb + A_STB + st * A_STAGE;
        size_t g = (size_t)(kt * 64 + frow) * HD;
#pragma unroll
        for (int ci = 0; ci < 2; ++ci) {
            int c = fcb + ci;
            uint32_t off = (uint32_t)frow * 128 + (((uint32_t)(c ^ (frow & 7))) << 4);
            cpa16(sb + A_KH + off, kh_g + g + c * 8);
            cpa16(sb + A_KL + off, kl_g + g + c * 8);
            cpa16(sb + A_VH + off, vh_g + g + c * 8);
            cpa16(sb + A_VL + off, vl_g + g + c * 8);
        }
    };

    const int ktmax = 2 * qt + 2;            // always >= 2
    const int warp_last_row = q0 + wid * 16 + 15;

    fillkv(0, 0); CP_COMMIT();
    fillkv(1, 1); CP_COMMIT();

    int st = 0;
    for (int kt = 0; kt < ktmax; ++kt) {
        if (kt + 2 < ktmax) CP_WAIT(1); else CP_WAIT(0);
        __syncthreads();
        if (kt + 2 < ktmax) { fillkv((st + 2) % 3, kt + 2); CP_COMMIT(); }

        const int k0g = kt * 64;
        if (k0g <= warp_last_row) {
            const uint32_t sb = shb + A_STB + st * A_STAGE;

            // ---- S = Q K^T (compensated; pre-scaled by 0.125*log2e) ----
            float s[8][4];
#pragma unroll
            for (int nt = 0; nt < 8; ++nt)
#pragma unroll
                for (int e = 0; e < 4; ++e) s[nt][e] = 0.0f;

#pragma unroll
            for (int ks = 0; ks < 4; ++ks) {
                uint32_t kh4[4][4], kl4[4][4];
#pragma unroll
                for (int np = 0; np < 4; ++np) {
                    int r = np * 16 + ((lane >> 4) << 3) + (lane & 7);
                    int g = ks * 2 + ((lane >> 3) & 1);
                    uint32_t off = (uint32_t)r * 128 + (((uint32_t)(g ^ (r & 7))) << 4);
                    ldsm4(kh4[np], sb + A_KH + off);
                    ldsm4(kl4[np], sb + A_KL + off);
                }
#pragma unroll
                for (int np = 0; np < 4; ++np)
#pragma unroll
                    for (int t = 0; t < 2; ++t)
                        mma_bf(s[np * 2 + t], qh[ks], kh4[np] + t * 2);
#pragma unroll
                for (int np = 0; np < 4; ++np)
#pragma unroll
                    for (int t = 0; t < 2; ++t)
                        mma_bf(s[np * 2 + t], ql[ks], kh4[np] + t * 2);
#pragma unroll
                for (int np = 0; np < 4; ++np)
#pragma unroll
                    for (int t = 0; t < 2; ++t)
                        mma_bf(s[np * 2 + t], qh[ks], kl4[np] + t * 2);
            }

            const int r0g = q0 + wid * 16 + (lane >> 2);
            const int r1g = r0g + 8;
            if (k0g + 63 > r0g) {
#pragma unroll
                for (int nt = 0; nt < 8; ++nt)
#pragma unroll
                    for (int e = 0; e < 2; ++e) {
                        int col = k0g + nt * 8 + ((lane & 3) << 1) + e;
                        if (col > r0g) s[nt][e]     = -1e30f;
                        if (col > r1g) s[nt][2 + e] = -1e30f;
                    }
            }

            // ---- online softmax (exp2 domain) ----
            float mx0 = -1e30f, mx1 = -1e30f;
#pragma unroll
            for (int nt = 0; nt < 8; ++nt) {
                mx0 = fmaxf(mx0, fmaxf(s[nt][0], s[nt][1]));
                mx1 = fmaxf(mx1, fmaxf(s[nt][2], s[nt][3]));
            }
            mx0 = fmaxf(mx0, __shfl_xor_sync(0xffffffffu, mx0, 1));
            mx0 = fmaxf(mx0, __shfl_xor_sync(0xffffffffu, mx0, 2));
            mx1 = fmaxf(mx1, __shfl_xor_sync(0xffffffffu, mx1, 1));
            mx1 = fmaxf(mx1, __shfl_xor_sync(0xffffffffu, mx1, 2));
            float mn0 = fmaxf(m0r, mx0), mn1 = fmaxf(m1r, mx1);
            float a0 = exp2f(m0r - mn0), a1 = exp2f(m1r - mn1);
            m0r = mn0; m1r = mn1;

            float sum0 = 0.0f, sum1 = 0.0f;
#pragma unroll
            for (int nt = 0; nt < 8; ++nt) {
                s[nt][0] = exp2f(s[nt][0] - mn0); sum0 += s[nt][0];
                s[nt][1] = exp2f(s[nt][1] - mn0); sum0 += s[nt][1];
                s[nt][2] = exp2f(s[nt][2] - mn1); sum1 += s[nt][2];
                s[nt][3] = exp2f(s[nt][3] - mn1); sum1 += s[nt][3];
            }
            sum0 += __shfl_xor_sync(0xffffffffu, sum0, 1);
            sum0 += __shfl_xor_sync(0xffffffffu, sum0, 2);
            sum1 += __shfl_xor_sync(0xffffffffu, sum1, 1);
            sum1 += __shfl_xor_sync(0xffffffffu, sum1, 2);
            l0r = l0r * a0 + sum0;
            l1r = l1r * a1 + sum1;
#pragma unroll
            for (int nt = 0; nt < 8; ++nt) {
                o[nt][0] *= a0; o[nt][1] *= a0;
                o[nt][2] *= a1; o[nt][3] *= a1;
            }

            // ---- O += P V (compensated, batched ldsm + 3 passes) ----
#pragma unroll
            for (int j = 0; j < 4; ++j) {
                uint32_t ph[4], plo[4];
#pragma unroll
                for (int t = 0; t < 2; ++t) {
                    int nt = j * 2 + t;
                    ph[t * 2 + 0]  = packhi(s[nt][0], s[nt][1]);
                    ph[t * 2 + 1]  = packhi(s[nt][2], s[nt][3]);
                    plo[t * 2 + 0] = packlo(s[nt][0], s[nt][1]);
                    plo[t * 2 + 1] = packlo(s[nt][2], s[nt][3]);
                }
                uint32_t vh4[4][4], vl4[4][4];
#pragma unroll
                for (int np = 0; np < 4; ++np) {
                    int r = j * 16 + (lane & 15);
                    int g = np * 2 + (lane >> 4);
                    uint32_t off = (uint32_t)r * 128 + (((uint32_t)(g ^ (r & 7))) << 4);
                    ldsm4t(vh4[np], sb + A_VH + off);
                    ldsm4t(vl4[np], sb + A_VL + off);
                }
#pragma unroll
                for (int np = 0; np < 4; ++np)
#pragma unroll
                    for (int t = 0; t < 2; ++t)
                        mma_bf(o[np * 2 + t], ph,  vh4[np] + t * 2);
#pragma unroll
                for (int np = 0; np < 4; ++np)
#pragma unroll
                    for (int t = 0; t < 2; ++t)
                        mma_bf(o[np * 2 + t], plo, vh4[np] + t * 2);
#pragma unroll
                for (int np = 0; np < 4; ++np)
#pragma unroll
                    for (int t = 0; t < 2; ++t)
                        mma_bf(o[np * 2 + t], ph,  vl4[np] + t * 2);
            }
        }
        st = (st + 1) % 3;
    }

    // ---- normalize and write split bf16 to [B,S,D] ----
    const float inv0 = 1.0f / l0r;
    const float inv1 = 1.0f / l1r;
    const int b  = bh >> 4;
    const int h_ = bh & 15;
    const int r0 = q0 + wid * 16 + (lane >> 2);
    size_t base0 = ((size_t)b * SS + r0) * DD + h_ * 64;
    size_t base1 = base0 + (size_t)8 * DD;
#pragma unroll
    for (int nt = 0; nt < 8; ++nt) {
        int col = nt * 8 + ((lane & 3) << 1);
        float v0x = o[nt][0] * inv0, v0y = o[nt][1] * inv0;
        float v1x = o[nt][2] * inv1, v1y = o[nt][3] * inv1;
        *(uint32_t*)&s_a_hi[base0 + col] = packhi(v0x, v0y);
        *(uint32_t*)&s_a_lo[base0 + col] = packlo(v0x, v0y);
        *(uint32_t*)&s_a_hi[base1 + col] = packhi(v1x, v1y);
        *(uint32_t*)&s_a_lo[base1 + col] = packlo(v1x, v1y);
    }
}

// ---------------------------------------------------------------------------
extern "C" void kernel_launch(void* const* d_in, const int* in_sizes, int n_in,
                              void* d_out, int out_size)
{
    const float* h  = (const float*)d_in[0];
    const float* Wq = (const float*)d_in[1];
    const float* bq = (const float*)d_in[2];
    const float* Wk = (const float*)d_in[3];
    const float* bk = (const float*)d_in[4];
    const float* Wv = (const float*)d_in[5];
    const float* bv = (const float*)d_in[6];
    const float* Wo = (const float*)d_in[7];
    const float* bo = (const float*)d_in[8];
    float* out = (float*)d_out;

    __nv_bfloat16 *hh, *hl, *wh, *wl, *qh, *qlp, *kh, *kl, *vh, *vl, *ah, *al;
    cudaGetSymbolAddress((void**)&hh,  s_h_hi);
    cudaGetSymbolAddress((void**)&hl,  s_h_lo);
    cudaGetSymbolAddress((void**)&wh,  s_w_hi);
    cudaGetSymbolAddress((void**)&wl,  s_w_lo);
    cudaGetSymbolAddress((void**)&qh,  s_q_hi);
    cudaGetSymbolAddress((void**)&qlp, s_q_lo);
    cudaGetSymbolAddress((void**)&kh,  s_k_hi);
    cudaGetSymbolAddress((void**)&kl,  s_k_lo);
    cudaGetSymbolAddress((void**)&vh,  s_v_hi);
    cudaGetSymbolAddress((void**)&vl,  s_v_lo);
    cudaGetSymbolAddress((void**)&ah,  s_a_hi);
    cudaGetSymbolAddress((void**)&al,  s_a_lo);

    cudaFuncSetAttribute(gemm_bf, cudaFuncAttributeMaxDynamicSharedMemorySize, G_SMEM);
    cudaFuncSetAttribute(attn_bf, cudaFuncAttributeMaxDynamicSharedMemorySize, A_SMEM);

    // ---- convert inputs to split bf16 (single launch) ----
    const int TOTAL4 = HN4 + 4 * WN4;   // 2097152
    split_all<<<TOTAL4 / 256, 256>>>(h, Wq, Wk, Wv, Wo, hh, hl, wh, wl);

    // ---- fused QKV projection (z selects q/k/v) ----
    dim3 qkv_grid(DD / 128, (BB * SS) / 128, 3);   // (8, 32, 3)
    gemm_bf<<<qkv_grid, 256, G_SMEM>>>(hh, hl, wh, wl,
                                       bq, bk, bv,
                                       qh, qlp, kh, kl, vh, vl,
                                       nullptr, 0);

    // ---- attention ----
    attn_bf<<<dim3(SS / 128, BB * HH), 256, A_SMEM>>>();

    // ---- output projection ----
    dim3 o_grid(DD / 128, (BB * SS) / 128, 1);
    gemm_bf<<<o_grid, 256, G_SMEM>>>(ah, al, wh + 3 * (size_t)DD * DD,
                                     wl + 3 * (size_t)DD * DD,
                                     bo, bo, bo,
                                     nullptr, nullptr, nullptr, nullptr,
                                     nullptr, nullptr,
                                     out, 1);
}

// round 12
// speedup vs baseline: 1.4786x; 1.2300x over previous
#include <cuda_runtime.h>
#include <cuda_bf16.h>
#include <cuda_fp16.h>
#include <cstdint>
#include <math.h>

#define BB 2
#define SS 2048
#define DD 1024
#define HH 16
#define HD 64
#define QSCALE 0.18033688011112042f   /* 0.125 * log2(e) */

// ---------------------------------------------------------------------------
// Persistent scratch.
// bf16 hi/lo (3-term path): h, Wq/Wk/Wv, q, k.
// fp16 single (1-term path): v, attn output, Wo.
// ---------------------------------------------------------------------------
__device__ __nv_bfloat16 s_h_hi[BB*SS*DD],    s_h_lo[BB*SS*DD];
__device__ __nv_bfloat16 s_w_hi[3*DD*DD],     s_w_lo[3*DD*DD];
__device__ __nv_bfloat16 s_q_hi[BB*HH*SS*HD], s_q_lo[BB*HH*SS*HD];
__device__ __nv_bfloat16 s_k_hi[BB*HH*SS*HD], s_k_lo[BB*HH*SS*HD];
__device__ __half        s_v_f16[BB*HH*SS*HD];
__device__ __half        s_a_f16[BB*SS*DD];
__device__ __half        s_wo_f16[DD*DD];

// ===========================================================================
// Helpers
// ===========================================================================
__device__ __forceinline__ uint32_t smem_u32(const void* p) {
    uint32_t a;
    asm("{ .reg .u64 t; cvta.to.shared.u64 t, %1; cvt.u32.u64 %0, t; }"
        : "=r"(a) : "l"(p));
    return a;
}
__device__ __forceinline__ void ldsm4(uint32_t* r, uint32_t a) {
    asm volatile("ldmatrix.sync.aligned.m8n8.x4.shared.b16 {%0,%1,%2,%3}, [%4];"
                 : "=r"(r[0]), "=r"(r[1]), "=r"(r[2]), "=r"(r[3]) : "r"(a));
}
__device__ __forceinline__ void ldsm4t(uint32_t* r, uint32_t a) {
    asm volatile("ldmatrix.sync.aligned.m8n8.x4.trans.shared.b16 {%0,%1,%2,%3}, [%4];"
                 : "=r"(r[0]), "=r"(r[1]), "=r"(r[2]), "=r"(r[3]) : "r"(a));
}
__device__ __forceinline__ void mma_bf(float* d, const uint32_t* a, const uint32_t* b) {
    asm volatile("mma.sync.aligned.m16n8k16.row.col.f32.bf16.bf16.f32 "
                 "{%0,%1,%2,%3}, {%4,%5,%6,%7}, {%8,%9}, {%0,%1,%2,%3};"
                 : "+f"(d[0]), "+f"(d[1]), "+f"(d[2]), "+f"(d[3])
                 : "r"(a[0]), "r"(a[1]), "r"(a[2]), "r"(a[3]),
                   "r"(b[0]), "r"(b[1]));
}
__device__ __forceinline__ void mma_f16(float* d, const uint32_t* a, const uint32_t* b) {
    asm volatile("mma.sync.aligned.m16n8k16.row.col.f32.f16.f16.f32 "
                 "{%0,%1,%2,%3}, {%4,%5,%6,%7}, {%8,%9}, {%0,%1,%2,%3};"
                 : "+f"(d[0]), "+f"(d[1]), "+f"(d[2]), "+f"(d[3])
                 : "r"(a[0]), "r"(a[1]), "r"(a[2]), "r"(a[3]),
                   "r"(b[0]), "r"(b[1]));
}
__device__ __forceinline__ uint32_t packhi(float x, float y) {
    uint32_t r;
    asm("prmt.b32 %0, %1, %2, 0x7632;"
        : "=r"(r) : "r"(__float_as_uint(x)), "r"(__float_as_uint(y)));
    return r;
}
__device__ __forceinline__ uint32_t packlo(float x, float y) {
    float lx = x - __uint_as_float(__float_as_uint(x) & 0xFFFF0000u);
    float ly = y - __uint_as_float(__float_as_uint(y) & 0xFFFF0000u);
    uint32_t r;
    asm("cvt.rn.bf16x2.f32 %0, %1, %2;" : "=r"(r) : "f"(ly), "f"(lx));
    return r;
}
// fp16x2 pack: lo half = x, hi half = y
__device__ __forceinline__ uint32_t packf16(float x, float y) {
    uint32_t r;
    asm("cvt.rn.f16x2.f32 %0, %1, %2;" : "=r"(r) : "f"(y), "f"(x));
    return r;
}
__device__ __forceinline__ void cpa16(uint32_t s, const void* g) {
    asm volatile("cp.async.cg.shared.global [%0], [%1], 16;"
                 :: "r"(s), "l"(g) : "memory");
}
#define CP_COMMIT() asm volatile("cp.async.commit_group;" ::: "memory")
#define CP_WAIT(n)  asm volatile("cp.async.wait_group %0;" :: "n"(n) : "memory")

// ===========================================================================
// Merged split pass: h + Wq/Wk/Wv -> bf16 hi/lo; Wo -> fp16. One launch.
// ===========================================================================
#define HN4 (BB * SS * DD / 4)
#define WN4 (DD * DD / 4)

__global__ __launch_bounds__(256) void split_all(
    const float* __restrict__ h,
    const float* __restrict__ Wq, const float* __restrict__ Wk,
    const float* __restrict__ Wv, const float* __restrict__ Wo,
    __nv_bfloat16* __restrict__ hh, __nv_bfloat16* __restrict__ hl,
    __nv_bfloat16* __restrict__ wh, __nv_bfloat16* __restrict__ wl,
    __half* __restrict__ wof)
{
    int i = blockIdx.x * blockDim.x + threadIdx.x;
    if (i < HN4) {
        float4 v = ((const float4*)h)[i];
        uint2 h4, l4;
        h4.x = packhi(v.x, v.y); h4.y = packhi(v.z, v.w);
        l4.x = packlo(v.x, v.y); l4.y = packlo(v.z, v.w);
        ((uint2*)hh)[i] = h4;
        ((uint2*)hl)[i] = l4;
        return;
    }
    int w = (i - HN4) >> 18;                // / WN4 (=262144)
    int j = (i - HN4) & (WN4 - 1);
    if (w < 3) {
        const float* src = (w == 0) ? Wq : (w == 1) ? Wk : Wv;
        float4 v = ((const float4*)src)[j];
        uint2 h4, l4;
        h4.x = packhi(v.x, v.y); h4.y = packhi(v.z, v.w);
        l4.x = packlo(v.x, v.y); l4.y = packlo(v.z, v.w);
        ((uint2*)(wh + (size_t)w * DD * DD))[j] = h4;
        ((uint2*)(wl + (size_t)w * DD * DD))[j] = l4;
    } else {
        float4 v = ((const float4*)Wo)[j];
        uint2 f4;
        f4.x = packf16(v.x, v.y); f4.y = packf16(v.z, v.w);
        ((uint2*)wof)[j] = f4;
    }
}

// ===========================================================================
// QKV GEMM: bf16 3-term compensation, 128x128x32 tile, 8 warps 4m x 2n,
// 3-stage cp.async, one sync per slab, 2 CTAs/SM.
// z=0 -> q (scaled, bf16 hi/lo); z=1 -> k (bf16 hi/lo); z=2 -> v (fp16).
// ===========================================================================
#define G_AH 0
#define G_AL 8192
#define G_BH 16384
#define G_BL 24576
#define G_STAGE 32768
#define G_SMEM  (3 * G_STAGE)          /* 98304 */

__global__ __launch_bounds__(256, 2) void gemm_qkv(
    const __nv_bfloat16* __restrict__ Ahi, const __nv_bfloat16* __restrict__ Alo,
    const __nv_bfloat16* __restrict__ Whi, const __nv_bfloat16* __restrict__ Wlo,
    const float* __restrict__ b0p, const float* __restrict__ b1p,
    const float* __restrict__ b2p,
    __nv_bfloat16* d0h, __nv_bfloat16* d0l,
    __nv_bfloat16* d1h, __nv_bfloat16* d1l,
    __half* d2f)
{
    extern __shared__ char sh[];
    const uint32_t shb = smem_u32(sh);
    const int tid  = threadIdx.x;
    const int lane = tid & 31;
    const int wid  = tid >> 5;
    const int wm   = wid & 3;
    const int wn   = wid >> 2;
    const int m0   = blockIdx.y * 128;
    const int n0   = blockIdx.x * 128;
    const int z    = blockIdx.z;

    const __nv_bfloat16* Wh = Whi + (size_t)z * DD * DD;
    const __nv_bfloat16* Wl = Wlo + (size_t)z * DD * DD;
    const float* bias = (z == 0) ? b0p : (z == 1) ? b1p : b2p;

    const int frow  = tid >> 1;
    const int cbase = (tid & 1) * 2;

    float acc[2][8][4];
#pragma unroll
    for (int mt = 0; mt < 2; ++mt)
#pragma unroll
        for (int nt = 0; nt < 8; ++nt)
#pragma unroll
            for (int e = 0; e < 4; ++e) acc[mt][nt][e] = 0.0f;

    auto fill = [&](int st, int kb) {
        uint32_t sb = shb + st * G_STAGE;
        size_t ga = (size_t)(m0 + frow) * DD + kb * 32;
        size_t gb = (size_t)(n0 + frow) * DD + kb * 32;
#pragma unroll
        for (int ci = 0; ci < 2; ++ci) {
            int c = cbase + ci;
            uint32_t off = (uint32_t)frow * 64 + (((uint32_t)(c ^ (frow & 3))) << 4);
            cpa16(sb + G_AH + off, Ahi + ga + c * 8);
            cpa16(sb + G_AL + off, Alo + ga + c * 8);
            cpa16(sb + G_BH + off, Wh + gb + c * 8);
            cpa16(sb + G_BL + off, Wl + gb + c * 8);
        }
    };

    fill(0, 0); CP_COMMIT();
    fill(1, 1); CP_COMMIT();

    const int KB = DD / 32;
    int st = 0;
    for (int kb = 0; kb < KB; ++kb) {
        if (kb + 2 < KB) CP_WAIT(1); else CP_WAIT(0);
        __syncthreads();
        if (kb + 2 < KB) { fill((st + 2) % 3, kb + 2); CP_COMMIT(); }

        const uint32_t sb = shb + st * G_STAGE;
#pragma unroll
        for (int ks = 0; ks < 2; ++ks) {
            uint32_t ah[2][4], al[2][4];
#pragma unroll
            for (int mt = 0; mt < 2; ++mt) {
                int r = wm * 32 + mt * 16 + (lane & 15);
                int g = ks * 2 + (lane >> 4);
                uint32_t off = (uint32_t)r * 64 + (((uint32_t)(g ^ (r & 3))) << 4);
                ldsm4(ah[mt], sb + G_AH + off);
                ldsm4(al[mt], sb + G_AL + off);
            }
#pragma unroll
            for (int np = 0; np < 4; ++np) {
                int r = wn * 64 + np * 16 + ((lane >> 4) << 3) + (lane & 7);
                int g = ks * 2 + ((lane >> 3) & 1);
                uint32_t off = (uint32_t)r * 64 + (((uint32_t)(g ^ (r & 3))) << 4);
                uint32_t bh4[4], bl4[4];
                ldsm4(bh4, sb + G_BH + off);
                ldsm4(bl4, sb + G_BL + off);
#pragma unroll
                for (int mt = 0; mt < 2; ++mt)
#pragma unroll
                    for (int t = 0; t < 2; ++t)
                        mma_bf(acc[mt][np * 2 + t], ah[mt], bh4 + t * 2);
#pragma unroll
                for (int mt = 0; mt < 2; ++mt)
#pragma unroll
                    for (int t = 0; t < 2; ++t)
                        mma_bf(acc[mt][np * 2 + t], al[mt], bh4 + t * 2);
#pragma unroll
                for (int mt = 0; mt < 2; ++mt)
#pragma unroll
                    for (int t = 0; t < 2; ++t)
                        mma_bf(acc[mt][np * 2 + t], ah[mt], bl4 + t * 2);
            }
        }
        st = (st + 1) % 3;
    }

    // ---- epilogue: head-major; q scaled; v stored fp16 ----
    const float scale = (z == 0) ? QSCALE : 1.0f;
#pragma unroll
    for (int mt = 0; mt < 2; ++mt) {
        int r0 = m0 + wm * 32 + mt * 16 + (lane >> 2);
        int r1 = r0 + 8;
#pragma unroll
        for (int nt = 0; nt < 8; ++nt) {
            int col = n0 + wn * 64 + nt * 8 + ((lane & 3) << 1);
            float2 bv = *(const float2*)&bias[col];
            float v0x = (acc[mt][nt][0] + bv.x) * scale;
            float v0y = (acc[mt][nt][1] + bv.y) * scale;
            float v1x = (acc[mt][nt][2] + bv.x) * scale;
            float v1y = (acc[mt][nt][3] + bv.y) * scale;
            int h_ = col >> 6, hd = col & 63;
            int b0 = r0 >> 11, ss0 = r0 & 2047;
            int b1 = r1 >> 11, ss1 = r1 & 2047;
            size_t i0 = ((size_t)(b0 * HH + h_) * SS + ss0) * HD + hd;
            size_t i1 = ((size_t)(b1 * HH + h_) * SS + ss1) * HD + hd;
            if (z == 2) {
                *(uint32_t*)&d2f[i0] = packf16(v0x, v0y);
                *(uint32_t*)&d2f[i1] = packf16(v1x, v1y);
            } else {
                __nv_bfloat16* dh = (z == 0) ? d0h : d1h;
                __nv_bfloat16* dl = (z == 0) ? d0l : d1l;
                *(uint32_t*)&dh[i0] = packhi(v0x, v0y);
                *(uint32_t*)&dl[i0] = packlo(v0x, v0y);
                *(uint32_t*)&dh[i1] = packhi(v1x, v1y);
                *(uint32_t*)&dl[i1] = packlo(v1x, v1y);
            }
        }
    }
}

// ===========================================================================
// Flash attention: QK bf16 3-term, PV fp16 1-term. 3-stage K/V pipeline,
// reversed q-tile order (LPT), output fp16 to s_a_f16.
// Stage: K hi 8KB + K lo 8KB + V fp16 8KB = 24KB.
// ===========================================================================
#define A_QH 0
#define A_QL 16384
#define A_KH 0
#define A_KL 8192
#define A_VF 16384
#define A_STAGE 24576
#define A_STB   32768
#define A_SMEM  (A_STB + 3 * A_STAGE)  /* 106496 */

__global__ __launch_bounds__(256) void attn_bf()
{
    extern __shared__ char sh[];
    const uint32_t shb = smem_u32(sh);
    const int tid  = threadIdx.x;
    const int lane = tid & 31;
    const int wid  = tid >> 5;
    const int qt   = (int)gridDim.x - 1 - (int)blockIdx.x;   // heavy tiles first
    const int bh   = blockIdx.y;
    const int q0   = qt * 128;

    const __nv_bfloat16* qh_g = s_q_hi + (size_t)bh * SS * HD;
    const __nv_bfloat16* ql_g = s_q_lo + (size_t)bh * SS * HD;
    const __nv_bfloat16* kh_g = s_k_hi + (size_t)bh * SS * HD;
    const __nv_bfloat16* kl_g = s_k_lo + (size_t)bh * SS * HD;
    const __half*        vf_g = s_v_f16 + (size_t)bh * SS * HD;

    // ---- stage Q (hi/lo), ldsm to registers ----
    {
        int row = tid >> 1;
        int cb  = (tid & 1) * 4;
        size_t g = (size_t)(q0 + row) * HD;
#pragma unroll
        for (int ci = 0; ci < 4; ++ci) {
            int c = cb + ci;
            uint32_t off = (uint32_t)row * 128 + (((uint32_t)(c ^ (row & 7))) << 4);
            cpa16(shb + A_QH + off, qh_g + g + c * 8);
            cpa16(shb + A_QL + off, ql_g + g + c * 8);
        }
    }
    CP_COMMIT();
    CP_WAIT(0);
    __syncthreads();

    uint32_t qh[4][4], ql[4][4];
#pragma unroll
    for (int ks = 0; ks < 4; ++ks) {
        int r = wid * 16 + (lane & 15);
        int g = ks * 2 + (lane >> 4);
        uint32_t off = (uint32_t)r * 128 + (((uint32_t)(g ^ (r & 7))) << 4);
        ldsm4(qh[ks], shb + A_QH + off);
        ldsm4(ql[ks], shb + A_QL + off);
    }

    float o[8][4];
#pragma unroll
    for (int nt = 0; nt < 8; ++nt)
#pragma unroll
        for (int e = 0; e < 4; ++e) o[nt][e] = 0.0f;
    float m0r = -1e30f, m1r = -1e30f, l0r = 0.0f, l1r = 0.0f;

    const int frow = tid >> 2;              // 0..63 (key row)
    const int fcb  = (tid & 3) * 2;         // 2 of 8 16B chunks per 128B row

    auto fillkv = [&](int st, int kt) {
        uint32_t sb = shb + A_STB + st * A_STAGE;
        size_t g = (size_t)(kt * 64 + frow) * HD;
#pragma unroll
        for (int ci = 0; ci < 2; ++ci) {
            int c = fcb + ci;
            uint32_t off = (uint32_t)frow * 128 + (((uint32_t)(c ^ (frow & 7))) << 4);
            cpa16(sb + A_KH + off, kh_g + g + c * 8);
            cpa16(sb + A_KL + off, kl_g + g + c * 8);
            cpa16(sb + A_VF + off, vf_g + g + c * 8);
        }
    };

    const int ktmax = 2 * qt + 2;
    const int warp_last_row = q0 + wid * 16 + 15;

    fillkv(0, 0); CP_COMMIT();
    fillkv(1, 1); CP_COMMIT();

    int st = 0;
    for (int kt = 0; kt < ktmax; ++kt) {
        if (kt + 2 < ktmax) CP_WAIT(1); else CP_WAIT(0);
        __syncthreads();
        if (kt + 2 < ktmax) { fillkv((st + 2) % 3, kt + 2); CP_COMMIT(); }

        const int k0g = kt * 64;
        if (k0g <= warp_last_row) {
            const uint32_t sb = shb + A_STB + st * A_STAGE;

            // ---- S = Q K^T (bf16 3-term; pre-scaled by 0.125*log2e) ----
            float s[8][4];
#pragma unroll
            for (int nt = 0; nt < 8; ++nt)
#pragma unroll
                for (int e = 0; e < 4; ++e) s[nt][e] = 0.0f;

#pragma unroll
            for (int ks = 0; ks < 4; ++ks) {
                uint32_t kh4[4][4], kl4[4][4];
#pragma unroll
                for (int np = 0; np < 4; ++np) {
                    int r = np * 16 + ((lane >> 4) << 3) + (lane & 7);
                    int g = ks * 2 + ((lane >> 3) & 1);
                    uint32_t off = (uint32_t)r * 128 + (((uint32_t)(g ^ (r & 7))) << 4);
                    ldsm4(kh4[np], sb + A_KH + off);
                    ldsm4(kl4[np], sb + A_KL + off);
                }
#pragma unroll
                for (int np = 0; np < 4; ++np)
#pragma unroll
                    for (int t = 0; t < 2; ++t)
                        mma_bf(s[np * 2 + t], qh[ks], kh4[np] + t * 2);
#pragma unroll
                for (int np = 0; np < 4; ++np)
#pragma unroll
                    for (int t = 0; t < 2; ++t)
                        mma_bf(s[np * 2 + t], ql[ks], kh4[np] + t * 2);
#pragma unroll
                for (int np = 0; np < 4; ++np)
#pragma unroll
                    for (int t = 0; t < 2; ++t)
                        mma_bf(s[np * 2 + t], qh[ks], kl4[np] + t * 2);
            }

            const int r0g = q0 + wid * 16 + (lane >> 2);
            const int r1g = r0g + 8;
            if (k0g + 63 > r0g) {
#pragma unroll
                for (int nt = 0; nt < 8; ++nt)
#pragma unroll
                    for (int e = 0; e < 2; ++e) {
                        int col = k0g + nt * 8 + ((lane & 3) << 1) + e;
                        if (col > r0g) s[nt][e]     = -1e30f;
                        if (col > r1g) s[nt][2 + e] = -1e30f;
                    }
            }

            // ---- online softmax (exp2 domain) ----
            float mx0 = -1e30f, mx1 = -1e30f;
#pragma unroll
            for (int nt = 0; nt < 8; ++nt) {
                mx0 = fmaxf(mx0, fmaxf(s[nt][0], s[nt][1]));
                mx1 = fmaxf(mx1, fmaxf(s[nt][2], s[nt][3]));
            }
            mx0 = fmaxf(mx0, __shfl_xor_sync(0xffffffffu, mx0, 1));
            mx0 = fmaxf(mx0, __shfl_xor_sync(0xffffffffu, mx0, 2));
            mx1 = fmaxf(mx1, __shfl_xor_sync(0xffffffffu, mx1, 1));
            mx1 = fmaxf(mx1, __shfl_xor_sync(0xffffffffu, mx1, 2));
            float mn0 = fmaxf(m0r, mx0), mn1 = fmaxf(m1r, mx1);
            float a0 = exp2f(m0r - mn0), a1 = exp2f(m1r - mn1);
            m0r = mn0; m1r = mn1;

            float sum0 = 0.0f, sum1 = 0.0f;
#pragma unroll
            for (int nt = 0; nt < 8; ++nt) {
                s[nt][0] = exp2f(s[nt][0] - mn0); sum0 += s[nt][0];
                s[nt][1] = exp2f(s[nt][1] - mn0); sum0 += s[nt][1];
                s[nt][2] = exp2f(s[nt][2] - mn1); sum1 += s[nt][2];
                s[nt][3] = exp2f(s[nt][3] - mn1); sum1 += s[nt][3];
            }
            sum0 += __shfl_xor_sync(0xffffffffu, sum0, 1);
            sum0 += __shfl_xor_sync(0xffffffffu, sum0, 2);
            sum1 += __shfl_xor_sync(0xffffffffu, sum1, 1);
            sum1 += __shfl_xor_sync(0xffffffffu, sum1, 2);
            l0r = l0r * a0 + sum0;
            l1r = l1r * a1 + sum1;
#pragma unroll
            for (int nt = 0; nt < 8; ++nt) {
                o[nt][0] *= a0; o[nt][1] *= a0;
                o[nt][2] *= a1; o[nt][3] *= a1;
            }

            // ---- O += P V (fp16 single MMA) ----
#pragma unroll
            for (int j = 0; j < 4; ++j) {
                uint32_t ph[4];
#pragma unroll
                for (int t = 0; t < 2; ++t) {
                    int nt = j * 2 + t;
                    ph[t * 2 + 0] = packf16(s[nt][0], s[nt][1]);
                    ph[t * 2 + 1] = packf16(s[nt][2], s[nt][3]);
                }
                uint32_t vh4[4][4];
#pragma unroll
                for (int np = 0; np < 4; ++np) {
                    int r = j * 16 + (lane & 15);
                    int g = np * 2 + (lane >> 4);
                    uint32_t off = (uint32_t)r * 128 + (((uint32_t)(g ^ (r & 7))) << 4);
                    ldsm4t(vh4[np], sb + A_VF + off);
                }
#pragma unroll
                for (int np = 0; np < 4; ++np)
#pragma unroll
                    for (int t = 0; t < 2; ++t)
                        mma_f16(o[np * 2 + t], ph, vh4[np] + t * 2);
            }
        }
        st = (st + 1) % 3;
    }

    // ---- normalize, write fp16 [B,S,D] ----
    const float inv0 = 1.0f / l0r;
    const float inv1 = 1.0f / l1r;
    const int b  = bh >> 4;
    const int h_ = bh & 15;
    const int r0 = q0 + wid * 16 + (lane >> 2);
    size_t base0 = ((size_t)b * SS + r0) * DD + h_ * 64;
    size_t base1 = base0 + (size_t)8 * DD;
#pragma unroll
    for (int nt = 0; nt < 8; ++nt) {
        int col = nt * 8 + ((lane & 3) << 1);
        *(uint32_t*)&s_a_f16[base0 + col] = packf16(o[nt][0] * inv0, o[nt][1] * inv0);
        *(uint32_t*)&s_a_f16[base1 + col] = packf16(o[nt][2] * inv1, o[nt][3] * inv1);
    }
}

// ===========================================================================
// O-projection: fp16 single-MMA NT GEMM. 128x128x(BK=64), 3-stage cp.async,
// 2 CTAs/SM. out = A @ Wo^T + bo (fp32).
// ===========================================================================
#define O_A 0
#define O_B 16384
#define O_STAGE 32768
#define O_SMEM  (3 * O_STAGE)          /* 98304 */

__global__ __launch_bounds__(256, 2) void gemm_of(
    const __half* __restrict__ A, const __half* __restrict__ W,
    const float* __restrict__ bias, float* __restrict__ out)
{
    extern __shared__ char sh[];
    const uint32_t shb = smem_u32(sh);
    const int tid  = threadIdx.x;
    const int lane = tid & 31;
    const int wid  = tid >> 5;
    const int wm   = wid & 3;
    const int wn   = wid >> 2;
    const int m0   = blockIdx.y * 128;
    const int n0   = blockIdx.x * 128;

    const int frow = tid >> 1;
    const int cb   = (tid & 1) * 4;

    float acc[2][8][4];
#pragma unroll
    for (int mt = 0; mt < 2; ++mt)
#pragma unroll
        for (int nt = 0; nt < 8; ++nt)
#pragma unroll
            for (int e = 0; e < 4; ++e) acc[mt][nt][e] = 0.0f;

    auto fill = [&](int st, int kb) {
        uint32_t sb = shb + st * O_STAGE;
        size_t ga = (size_t)(m0 + frow) * DD + kb * 64;
        size_t gb = (size_t)(n0 + frow) * DD + kb * 64;
#pragma unroll
        for (int ci = 0; ci < 4; ++ci) {
            int c = cb + ci;
            uint32_t off = (uint32_t)frow * 128 + (((uint32_t)(c ^ (frow & 7))) << 4);
            cpa16(sb + O_A + off, A + ga + c * 8);
            cpa16(sb + O_B + off, W + gb + c * 8);
        }
    };

    fill(0, 0); CP_COMMIT();
    fill(1, 1); CP_COMMIT();

    const int KB = DD / 64;   // 16
    int st = 0;
    for (int kb = 0; kb < KB; ++kb) {
        if (kb + 2 < KB) CP_WAIT(1); else CP_WAIT(0);
        __syncthreads();
        if (kb + 2 < KB) { fill((st + 2) % 3, kb + 2); CP_COMMIT(); }

        const uint32_t sb = shb + st * O_STAGE;
#pragma unroll
        for (int ks = 0; ks < 4; ++ks) {
            uint32_t af[2][4];
#pragma unroll
            for (int mt = 0; mt < 2; ++mt) {
                int r = wm * 32 + mt * 16 + (lane & 15);
                int g = ks * 2 + (lane >> 4);
                uint32_t off = (uint32_t)r * 128 + (((uint32_t)(g ^ (r & 7))) << 4);
                ldsm4(af[mt], sb + O_A + off);
            }
#pragma unroll
            for (int np = 0; np < 4; ++np) {
                int r = wn * 64 + np * 16 + ((lane >> 4) << 3) + (lane & 7);
                int g = ks * 2 + ((lane >> 3) & 1);
                uint32_t off = (uint32_t)r * 128 + (((uint32_t)(g ^ (r & 7))) << 4);
                uint32_t bf4[4];
                ldsm4(bf4, sb + O_B + off);
#pragma unroll
                for (int mt = 0; mt < 2; ++mt)
#pragma unroll
                    for (int t = 0; t < 2; ++t)
                        mma_f16(acc[mt][np * 2 + t], af[mt], bf4 + t * 2);
            }
        }
        st = (st + 1) % 3;
    }

#pragma unroll
    for (int mt = 0; mt < 2; ++mt) {
        int r0 = m0 + wm * 32 + mt * 16 + (lane >> 2);
        int r1 = r0 + 8;
#pragma unroll
        for (int nt = 0; nt < 8; ++nt) {
            int col = n0 + wn * 64 + nt * 8 + ((lane & 3) << 1);
            float2 bv = *(const float2*)&bias[col];
            float2 o0 = { acc[mt][nt][0] + bv.x, acc[mt][nt][1] + bv.y };
            float2 o1 = { acc[mt][nt][2] + bv.x, acc[mt][nt][3] + bv.y };
            *(float2*)&out[(size_t)r0 * DD + col] = o0;
            *(float2*)&out[(size_t)r1 * DD + col] = o1;
        }
    }
}

// ---------------------------------------------------------------------------
extern "C" void kernel_launch(void* const* d_in, const int* in_sizes, int n_in,
                              void* d_out, int out_size)
{
    const float* h  = (const float*)d_in[0];
    const float* Wq = (const float*)d_in[1];
    const float* bq = (const float*)d_in[2];
    const float* Wk = (const float*)d_in[3];
    const float* bk = (const float*)d_in[4];
    const float* Wv = (const float*)d_in[5];
    const float* bv = (const float*)d_in[6];
    const float* Wo = (const float*)d_in[7];
    const float* bo = (const float*)d_in[8];
    float* out = (float*)d_out;

    __nv_bfloat16 *hh, *hl, *wh, *wl, *qh, *qlp, *kh, *kl;
    __half *vf, *af, *wof;
    cudaGetSymbolAddress((void**)&hh,  s_h_hi);
    cudaGetSymbolAddress((void**)&hl,  s_h_lo);
    cudaGetSymbolAddress((void**)&wh,  s_w_hi);
    cudaGetSymbolAddress((void**)&wl,  s_w_lo);
    cudaGetSymbolAddress((void**)&qh,  s_q_hi);
    cudaGetSymbolAddress((void**)&qlp, s_q_lo);
    cudaGetSymbolAddress((void**)&kh,  s_k_hi);
    cudaGetSymbolAddress((void**)&kl,  s_k_lo);
    cudaGetSymbolAddress((void**)&vf,  s_v_f16);
    cudaGetSymbolAddress((void**)&af,  s_a_f16);
    cudaGetSymbolAddress((void**)&wof, s_wo_f16);

    cudaFuncSetAttribute(gemm_qkv, cudaFuncAttributeMaxDynamicSharedMemorySize, G_SMEM);
    cudaFuncSetAttribute(attn_bf,  cudaFuncAttributeMaxDynamicSharedMemorySize, A_SMEM);
    cudaFuncSetAttribute(gemm_of,  cudaFuncAttributeMaxDynamicSharedMemorySize, O_SMEM);

    const int TOTAL4 = HN4 + 4 * WN4;
    split_all<<<TOTAL4 / 256, 256>>>(h, Wq, Wk, Wv, Wo, hh, hl, wh, wl, wof);

    dim3 qkv_grid(DD / 128, (BB * SS) / 128, 3);
    gemm_qkv<<<qkv_grid, 256, G_SMEM>>>(hh, hl, wh, wl,
                                        bq, bk, bv,
                                        qh, qlp, kh, kl, vf);

    attn_bf<<<dim3(SS / 128, BB * HH), 256, A_SMEM>>>();

    gemm_of<<<dim3(DD / 128, (BB * SS) / 128), 256, O_SMEM>>>(af, wof, bo, out);
}

// round 13
// speedup vs baseline: 2.8445x; 1.9237x over previous
#include <cuda_runtime.h>
#include <cuda_fp16.h>
#include <cstdint>
#include <math.h>

#define BB 2
#define SS 2048
#define DD 1024
#define HH 16
#define HD 64
#define QSCALE 0.18033688011112042f   /* 0.125 * log2(e) */

// ---------------------------------------------------------------------------
// Persistent fp16 scratch
// ---------------------------------------------------------------------------
__device__ __half s_h_f16[BB*SS*DD];
__device__ __half s_w_f16[4*DD*DD];
__device__ __half s_q[BB*HH*SS*HD];
__device__ __half s_k[BB*HH*SS*HD];
__device__ __half s_v[BB*HH*SS*HD];
__device__ __half s_a_f16[BB*SS*DD];

// ===========================================================================
// Helpers
// ===========================================================================
__device__ __forceinline__ uint32_t smem_u32(const void* p) {
    uint32_t a;
    asm("{ .reg .u64 t; cvta.to.shared.u64 t, %1; cvt.u32.u64 %0, t; }"
        : "=r"(a) : "l"(p));
    return a;
}
__device__ __forceinline__ void ldsm4(uint32_t* r, uint32_t a) {
    asm volatile("ldmatrix.sync.aligned.m8n8.x4.shared.b16 {%0,%1,%2,%3}, [%4];"
                 : "=r"(r[0]), "=r"(r[1]), "=r"(r[2]), "=r"(r[3]) : "r"(a));
}
__device__ __forceinline__ void ldsm4t(uint32_t* r, uint32_t a) {
    asm volatile("ldmatrix.sync.aligned.m8n8.x4.trans.shared.b16 {%0,%1,%2,%3}, [%4];"
                 : "=r"(r[0]), "=r"(r[1]), "=r"(r[2]), "=r"(r[3]) : "r"(a));
}
__device__ __forceinline__ void mma_f16(float* d, const uint32_t* a, const uint32_t* b) {
    asm volatile("mma.sync.aligned.m16n8k16.row.col.f32.f16.f16.f32 "
                 "{%0,%1,%2,%3}, {%4,%5,%6,%7}, {%8,%9}, {%0,%1,%2,%3};"
                 : "+f"(d[0]), "+f"(d[1]), "+f"(d[2]), "+f"(d[3])
                 : "r"(a[0]), "r"(a[1]), "r"(a[2]), "r"(a[3]),
                   "r"(b[0]), "r"(b[1]));
}
// fp16x2 pack: lo half = x, hi half = y
__device__ __forceinline__ uint32_t packf16(float x, float y) {
    uint32_t r;
    asm("cvt.rn.f16x2.f32 %0, %1, %2;" : "=r"(r) : "f"(y), "f"(x));
    return r;
}
__device__ __forceinline__ void cpa16(uint32_t s, const void* g) {
    asm volatile("cp.async.cg.shared.global [%0], [%1], 16;"
                 :: "r"(s), "l"(g) : "memory");
}
#define CP_COMMIT() asm volatile("cp.async.commit_group;" ::: "memory")
#define CP_WAIT(n)  asm volatile("cp.async.wait_group %0;" :: "n"(n) : "memory")

// ===========================================================================
// Merged convert pass: h + 4 weights -> fp16, one launch
// ===========================================================================
#define HN4 (BB * SS * DD / 4)
#define WN4 (DD * DD / 4)

__global__ __launch_bounds__(256) void split_all(
    const float* __restrict__ h,
    const float* __restrict__ Wq, const float* __restrict__ Wk,
    const float* __restrict__ Wv, const float* __restrict__ Wo,
    __half* __restrict__ hf, __half* __restrict__ wf)
{
    int i = blockIdx.x * blockDim.x + threadIdx.x;
    const float* src;
    __half* dst;
    int j;
    if (i < HN4) {
        src = h; dst = hf; j = i;
    } else {
        int w = (i - HN4) >> 18;            // / WN4 (=262144)
        j = (i - HN4) & (WN4 - 1);
        src = (w == 0) ? Wq : (w == 1) ? Wk : (w == 2) ? Wv : Wo;
        dst = wf + (size_t)w * DD * DD;
    }
    float4 v = ((const float4*)src)[j];
    uint2 f4;
    f4.x = packf16(v.x, v.y); f4.y = packf16(v.z, v.w);
    ((uint2*)dst)[j] = f4;
}

// ===========================================================================
// fp16 NT GEMM: C[m,n] = sum_k A[m,k]*W[n,k] + bias[n]
// 128x128x(BK=64) tile, 8 warps 4m x 2n, 3-stage cp.async, 2 CTAs/SM.
// mode 0: head-major fp16 store (z: 0=q scaled, 1=k, 2=v)
// mode 1: fp32 [row,col] store to fout.
// ===========================================================================
#define G_A 0
#define G_B 16384
#define G_STAGE 32768
#define G_SMEM  (3 * G_STAGE)          /* 98304 */

__global__ __launch_bounds__(256, 2) void gemm_f16(
    const __half* __restrict__ A, const __half* __restrict__ Wbase,
    const float* __restrict__ b0p, const float* __restrict__ b1p,
    const float* __restrict__ b2p,
    __half* d0, __half* d1, __half* d2,
    float* fout, int mode)
{
    extern __shared__ char sh[];
    const uint32_t shb = smem_u32(sh);
    const int tid  = threadIdx.x;
    const int lane = tid & 31;
    const int wid  = tid >> 5;
    const int wm   = wid & 3;
    const int wn   = wid >> 2;
    const int m0   = blockIdx.y * 128;
    const int n0   = blockIdx.x * 128;
    const int z    = blockIdx.z;

    const __half* W = Wbase + (size_t)z * DD * DD;
    const float* bias = (z == 0) ? b0p : (z == 1) ? b1p : b2p;

    const int frow = tid >> 1;
    const int cb   = (tid & 1) * 4;

    float acc[2][8][4];
#pragma unroll
    for (int mt = 0; mt < 2; ++mt)
#pragma unroll
        for (int nt = 0; nt < 8; ++nt)
#pragma unroll
            for (int e = 0; e < 4; ++e) acc[mt][nt][e] = 0.0f;

    auto fill = [&](int st, int kb) {
        uint32_t sb = shb + st * G_STAGE;
        size_t ga = (size_t)(m0 + frow) * DD + kb * 64;
        size_t gb = (size_t)(n0 + frow) * DD + kb * 64;
#pragma unroll
        for (int ci = 0; ci < 4; ++ci) {
            int c = cb + ci;
            uint32_t off = (uint32_t)frow * 128 + (((uint32_t)(c ^ (frow & 7))) << 4);
            cpa16(sb + G_A + off, A + ga + c * 8);
            cpa16(sb + G_B + off, W + gb + c * 8);
        }
    };

    fill(0, 0); CP_COMMIT();
    fill(1, 1); CP_COMMIT();

    const int KB = DD / 64;   // 16
    int st = 0;
    for (int kb = 0; kb < KB; ++kb) {
        if (kb + 2 < KB) CP_WAIT(1); else CP_WAIT(0);
        __syncthreads();
        if (kb + 2 < KB) { fill((st + 2) % 3, kb + 2); CP_COMMIT(); }

        const uint32_t sb = shb + st * G_STAGE;
#pragma unroll
        for (int ks = 0; ks < 4; ++ks) {
            uint32_t af[2][4];
#pragma unroll
            for (int mt = 0; mt < 2; ++mt) {
                int r = wm * 32 + mt * 16 + (lane & 15);
                int g = ks * 2 + (lane >> 4);
                uint32_t off = (uint32_t)r * 128 + (((uint32_t)(g ^ (r & 7))) << 4);
                ldsm4(af[mt], sb + G_A + off);
            }
#pragma unroll
            for (int np = 0; np < 4; ++np) {
                int r = wn * 64 + np * 16 + ((lane >> 4) << 3) + (lane & 7);
                int g = ks * 2 + ((lane >> 3) & 1);
                uint32_t off = (uint32_t)r * 128 + (((uint32_t)(g ^ (r & 7))) << 4);
                uint32_t bf4[4];
                ldsm4(bf4, sb + G_B + off);
#pragma unroll
                for (int mt = 0; mt < 2; ++mt)
#pragma unroll
                    for (int t = 0; t < 2; ++t)
                        mma_f16(acc[mt][np * 2 + t], af[mt], bf4 + t * 2);
            }
        }
        st = (st + 1) % 3;
    }

    // ---- epilogue ----
    const float scale = (mode == 0 && z == 0) ? QSCALE : 1.0f;
    __half* dst = (z == 0) ? d0 : (z == 1) ? d1 : d2;
#pragma unroll
    for (int mt = 0; mt < 2; ++mt) {
        int r0 = m0 + wm * 32 + mt * 16 + (lane >> 2);
        int r1 = r0 + 8;
#pragma unroll
        for (int nt = 0; nt < 8; ++nt) {
            int col = n0 + wn * 64 + nt * 8 + ((lane & 3) << 1);
            float2 bv = *(const float2*)&bias[col];
            float v0x = (acc[mt][nt][0] + bv.x) * scale;
            float v0y = (acc[mt][nt][1] + bv.y) * scale;
            float v1x = (acc[mt][nt][2] + bv.x) * scale;
            float v1y = (acc[mt][nt][3] + bv.y) * scale;
            if (mode == 0) {
                int h_ = col >> 6, hd = col & 63;
                int b0 = r0 >> 11, ss0 = r0 & 2047;
                int b1 = r1 >> 11, ss1 = r1 & 2047;
                size_t i0 = ((size_t)(b0 * HH + h_) * SS + ss0) * HD + hd;
                size_t i1 = ((size_t)(b1 * HH + h_) * SS + ss1) * HD + hd;
                *(uint32_t*)&dst[i0] = packf16(v0x, v0y);
                *(uint32_t*)&dst[i1] = packf16(v1x, v1y);
            } else {
                float2 o0 = { v0x, v0y }, o1 = { v1x, v1y };
                *(float2*)&fout[(size_t)r0 * DD + col] = o0;
                *(float2*)&fout[(size_t)r1 * DD + col] = o1;
            }
        }
    }
}

// ===========================================================================
// Flash attention, all fp16 single-MMA. Block = (b,h) x 128 q-rows, 8 warps.
// 3-stage K/V pipeline (16KB/stage), 2 CTAs/SM, LPT tile order.
// ===========================================================================
#define A_Q  0
#define A_K  0
#define A_V  8192
#define A_STAGE 16384
#define A_STB   16384
#define A_SMEM  (A_STB + 3 * A_STAGE)  /* 65536 */

__global__ __launch_bounds__(256, 2) void attn_f16()
{
    extern __shared__ char sh[];
    const uint32_t shb = smem_u32(sh);
    const int tid  = threadIdx.x;
    const int lane = tid & 31;
    const int wid  = tid >> 5;
    const int qt   = (int)gridDim.x - 1 - (int)blockIdx.x;   // heavy tiles first
    const int bh   = blockIdx.y;
    const int q0   = qt * 128;

    const __half* q_g = s_q + (size_t)bh * SS * HD;
    const __half* k_g = s_k + (size_t)bh * SS * HD;
    const __half* v_g = s_v + (size_t)bh * SS * HD;

    // ---- stage Q, ldsm to registers ----
    {
        int row = tid >> 1;
        int cb  = (tid & 1) * 4;
        size_t g = (size_t)(q0 + row) * HD;
#pragma unroll
        for (int ci = 0; ci < 4; ++ci) {
            int c = cb + ci;
            uint32_t off = (uint32_t)row * 128 + (((uint32_t)(c ^ (row & 7))) << 4);
            cpa16(shb + A_Q + off, q_g + g + c * 8);
        }
    }
    CP_COMMIT();
    CP_WAIT(0);
    __syncthreads();

    uint32_t qf[4][4];
#pragma unroll
    for (int ks = 0; ks < 4; ++ks) {
        int r = wid * 16 + (lane & 15);
        int g = ks * 2 + (lane >> 4);
        uint32_t off = (uint32_t)r * 128 + (((uint32_t)(g ^ (r & 7))) << 4);
        ldsm4(qf[ks], shb + A_Q + off);
    }
    __syncthreads();   // Q smem region reused? (no — stages start at A_STB) safe anyway

    float o[8][4];
#pragma unroll
    for (int nt = 0; nt < 8; ++nt)
#pragma unroll
        for (int e = 0; e < 4; ++e) o[nt][e] = 0.0f;
    float m0r = -1e30f, m1r = -1e30f, l0r = 0.0f, l1r = 0.0f;

    const int frow = tid >> 2;              // 0..63 key row
    const int fcb  = (tid & 3) * 2;

    auto fillkv = [&](int st, int kt) {
        uint32_t sb = shb + A_STB + st * A_STAGE;
        size_t g = (size_t)(kt * 64 + frow) * HD;
#pragma unroll
        for (int ci = 0; ci < 2; ++ci) {
            int c = fcb + ci;
            uint32_t off = (uint32_t)frow * 128 + (((uint32_t)(c ^ (frow & 7))) << 4);
            cpa16(sb + A_K + off, k_g + g + c * 8);
            cpa16(sb + A_V + off, v_g + g + c * 8);
        }
    };

    const int ktmax = 2 * qt + 2;
    const int warp_last_row = q0 + wid * 16 + 15;

    fillkv(0, 0); CP_COMMIT();
    fillkv(1, 1); CP_COMMIT();

    int st = 0;
    for (int kt = 0; kt < ktmax; ++kt) {
        if (kt + 2 < ktmax) CP_WAIT(1); else CP_WAIT(0);
        __syncthreads();
        if (kt + 2 < ktmax) { fillkv((st + 2) % 3, kt + 2); CP_COMMIT(); }

        const int k0g = kt * 64;
        if (k0g <= warp_last_row) {
            const uint32_t sb = shb + A_STB + st * A_STAGE;

            // ---- S = Q K^T (single fp16 MMA; Q pre-scaled by 0.125*log2e) ----
            float s[8][4];
#pragma unroll
            for (int nt = 0; nt < 8; ++nt)
#pragma unroll
                for (int e = 0; e < 4; ++e) s[nt][e] = 0.0f;

#pragma unroll
            for (int ks = 0; ks < 4; ++ks) {
#pragma unroll
                for (int np = 0; np < 4; ++np) {
                    int r = np * 16 + ((lane >> 4) << 3) + (lane & 7);
                    int g = ks * 2 + ((lane >> 3) & 1);
                    uint32_t off = (uint32_t)r * 128 + (((uint32_t)(g ^ (r & 7))) << 4);
                    uint32_t kf[4];
                    ldsm4(kf, sb + A_K + off);
#pragma unroll
                    for (int t = 0; t < 2; ++t)
                        mma_f16(s[np * 2 + t], qf[ks], kf + t * 2);
                }
            }

            const int r0g = q0 + wid * 16 + (lane >> 2);
            const int r1g = r0g + 8;
            if (k0g + 63 > r0g) {
#pragma unroll
                for (int nt = 0; nt < 8; ++nt)
#pragma unroll
                    for (int e = 0; e < 2; ++e) {
                        int col = k0g + nt * 8 + ((lane & 3) << 1) + e;
                        if (col > r0g) s[nt][e]     = -1e30f;
                        if (col > r1g) s[nt][2 + e] = -1e30f;
                    }
            }

            // ---- online softmax (exp2 domain) ----
            float mx0 = -1e30f, mx1 = -1e30f;
#pragma unroll
            for (int nt = 0; nt < 8; ++nt) {
                mx0 = fmaxf(mx0, fmaxf(s[nt][0], s[nt][1]));
                mx1 = fmaxf(mx1, fmaxf(s[nt][2], s[nt][3]));
            }
            mx0 = fmaxf(mx0, __shfl_xor_sync(0xffffffffu, mx0, 1));
            mx0 = fmaxf(mx0, __shfl_xor_sync(0xffffffffu, mx0, 2));
            mx1 = fmaxf(mx1, __shfl_xor_sync(0xffffffffu, mx1, 1));
            mx1 = fmaxf(mx1, __shfl_xor_sync(0xffffffffu, mx1, 2));
            float mn0 = fmaxf(m0r, mx0), mn1 = fmaxf(m1r, mx1);
            float a0 = exp2f(m0r - mn0), a1 = exp2f(m1r - mn1);
            m0r = mn0; m1r = mn1;

            float sum0 = 0.0f, sum1 = 0.0f;
#pragma unroll
            for (int nt = 0; nt < 8; ++nt) {
                s[nt][0] = exp2f(s[nt][0] - mn0); sum0 += s[nt][0];
                s[nt][1] = exp2f(s[nt][1] - mn0); sum0 += s[nt][1];
                s[nt][2] = exp2f(s[nt][2] - mn1); sum1 += s[nt][2];
                s[nt][3] = exp2f(s[nt][3] - mn1); sum1 += s[nt][3];
            }
            sum0 += __shfl_xor_sync(0xffffffffu, sum0, 1);
            sum0 += __shfl_xor_sync(0xffffffffu, sum0, 2);
            sum1 += __shfl_xor_sync(0xffffffffu, sum1, 1);
            sum1 += __shfl_xor_sync(0xffffffffu, sum1, 2);
            l0r = l0r * a0 + sum0;
            l1r = l1r * a1 + sum1;
#pragma unroll
            for (int nt = 0; nt < 8; ++nt) {
                o[nt][0] *= a0; o[nt][1] *= a0;
                o[nt][2] *= a1; o[nt][3] *= a1;
            }

            // ---- O += P V (fp16 single MMA) ----
#pragma unroll
            for (int j = 0; j < 4; ++j) {
                uint32_t ph[4];
#pragma unroll
                for (int t = 0; t < 2; ++t) {
                    int nt = j * 2 + t;
                    ph[t * 2 + 0] = packf16(s[nt][0], s[nt][1]);
                    ph[t * 2 + 1] = packf16(s[nt][2], s[nt][3]);
                }
#pragma unroll
                for (int np = 0; np < 4; ++np) {
                    int r = j * 16 + (lane & 15);
                    int g = np * 2 + (lane >> 4);
                    uint32_t off = (uint32_t)r * 128 + (((uint32_t)(g ^ (r & 7))) << 4);
                    uint32_t vf[4];
                    ldsm4t(vf, sb + A_V + off);
#pragma unroll
                    for (int t = 0; t < 2; ++t)
                        mma_f16(o[np * 2 + t], ph, vf + t * 2);
                }
            }
        }
        st = (st + 1) % 3;
    }

    // ---- normalize, write fp16 [B,S,D] ----
    const float inv0 = 1.0f / l0r;
    const float inv1 = 1.0f / l1r;
    const int b  = bh >> 4;
    const int h_ = bh & 15;
    const int r0 = q0 + wid * 16 + (lane >> 2);
    size_t base0 = ((size_t)b * SS + r0) * DD + h_ * 64;
    size_t base1 = base0 + (size_t)8 * DD;
#pragma unroll
    for (int nt = 0; nt < 8; ++nt) {
        int col = nt * 8 + ((lane & 3) << 1);
        *(uint32_t*)&s_a_f16[base0 + col] = packf16(o[nt][0] * inv0, o[nt][1] * inv0);
        *(uint32_t*)&s_a_f16[base1 + col] = packf16(o[nt][2] * inv1, o[nt][3] * inv1);
    }
}

// ---------------------------------------------------------------------------
extern "C" void kernel_launch(void* const* d_in, const int* in_sizes, int n_in,
                              void* d_out, int out_size)
{
    const float* h  = (const float*)d_in[0];
    const float* Wq = (const float*)d_in[1];
    const float* bq = (const float*)d_in[2];
    const float* Wk = (const float*)d_in[3];
    const float* bk = (const float*)d_in[4];
    const float* Wv = (const float*)d_in[5];
    const float* bv = (const float*)d_in[6];
    const float* Wo = (const float*)d_in[7];
    const float* bo = (const float*)d_in[8];
    float* out = (float*)d_out;

    __half *hf, *wf, *qp, *kp, *vp, *af;
    cudaGetSymbolAddress((void**)&hf, s_h_f16);
    cudaGetSymbolAddress((void**)&wf, s_w_f16);
    cudaGetSymbolAddress((void**)&qp, s_q);
    cudaGetSymbolAddress((void**)&kp, s_k);
    cudaGetSymbolAddress((void**)&vp, s_v);
    cudaGetSymbolAddress((void**)&af, s_a_f16);

    cudaFuncSetAttribute(gemm_f16, cudaFuncAttributeMaxDynamicSharedMemorySize, G_SMEM);
    cudaFuncSetAttribute(attn_f16, cudaFuncAttributeMaxDynamicSharedMemorySize, A_SMEM);

    const int TOTAL4 = HN4 + 4 * WN4;
    split_all<<<TOTAL4 / 256, 256>>>(h, Wq, Wk, Wv, Wo, hf, wf);

    // QKV projection (z = 0,1,2)
    dim3 qkv_grid(DD / 128, (BB * SS) / 128, 3);
    gemm_f16<<<qkv_grid, 256, G_SMEM>>>(hf, wf, bq, bk, bv,
                                        qp, kp, vp, nullptr, 0);

    attn_f16<<<dim3(SS / 128, BB * HH), 256, A_SMEM>>>();

    // O projection (Wo at offset 3)
    dim3 o_grid(DD / 128, (BB * SS) / 128, 1);
    gemm_f16<<<o_grid, 256, G_SMEM>>>(af, wf + 3 * (size_t)DD * DD,
                                      bo, bo, bo,
                                      nullptr, nullptr, nullptr,
                                      out, 1);
}

// round 14
// speedup vs baseline: 2.8768x; 1.0114x over previous
#include <cuda_runtime.h>
#include <cuda_fp16.h>
#include <cstdint>
#include <math.h>

#define BB 2
#define SS 2048
#define DD 1024
#define HH 16
#define HD 64
#define QSCALE 0.18033688011112042f   /* 0.125 * log2(e) */

// ---------------------------------------------------------------------------
// Persistent fp16 scratch
// ---------------------------------------------------------------------------
__device__ __half s_h_f16[BB*SS*DD];
__device__ __half s_w_f16[4*DD*DD];
__device__ __half s_q[BB*HH*SS*HD];
__device__ __half s_k[BB*HH*SS*HD];
__device__ __half s_v[BB*HH*SS*HD];
__device__ __half s_a_f16[BB*SS*DD];

// ===========================================================================
// Helpers
// ===========================================================================
__device__ __forceinline__ uint32_t smem_u32(const void* p) {
    uint32_t a;
    asm("{ .reg .u64 t; cvta.to.shared.u64 t, %1; cvt.u32.u64 %0, t; }"
        : "=r"(a) : "l"(p));
    return a;
}
__device__ __forceinline__ void ldsm4(uint32_t* r, uint32_t a) {
    asm volatile("ldmatrix.sync.aligned.m8n8.x4.shared.b16 {%0,%1,%2,%3}, [%4];"
                 : "=r"(r[0]), "=r"(r[1]), "=r"(r[2]), "=r"(r[3]) : "r"(a));
}
__device__ __forceinline__ void ldsm4t(uint32_t* r, uint32_t a) {
    asm volatile("ldmatrix.sync.aligned.m8n8.x4.trans.shared.b16 {%0,%1,%2,%3}, [%4];"
                 : "=r"(r[0]), "=r"(r[1]), "=r"(r[2]), "=r"(r[3]) : "r"(a));
}
__device__ __forceinline__ void mma_f16(float* d, const uint32_t* a, const uint32_t* b) {
    asm volatile("mma.sync.aligned.m16n8k16.row.col.f32.f16.f16.f32 "
                 "{%0,%1,%2,%3}, {%4,%5,%6,%7}, {%8,%9}, {%0,%1,%2,%3};"
                 : "+f"(d[0]), "+f"(d[1]), "+f"(d[2]), "+f"(d[3])
                 : "r"(a[0]), "r"(a[1]), "r"(a[2]), "r"(a[3]),
                   "r"(b[0]), "r"(b[1]));
}
// fp16x2 pack: lo half = x, hi half = y
__device__ __forceinline__ uint32_t packf16(float x, float y) {
    uint32_t r;
    asm("cvt.rn.f16x2.f32 %0, %1, %2;" : "=r"(r) : "f"(y), "f"(x));
    return r;
}
__device__ __forceinline__ void cpa16(uint32_t s, const void* g) {
    asm volatile("cp.async.cg.shared.global [%0], [%1], 16;"
                 :: "r"(s), "l"(g) : "memory");
}
#define CP_COMMIT() asm volatile("cp.async.commit_group;" ::: "memory")
#define CP_WAIT(n)  asm volatile("cp.async.wait_group %0;" :: "n"(n) : "memory")

// ===========================================================================
// Merged convert pass: h + 4 weights -> fp16, one launch
// ===========================================================================
#define HN4 (BB * SS * DD / 4)
#define WN4 (DD * DD / 4)

__global__ __launch_bounds__(256) void split_all(
    const float* __restrict__ h,
    const float* __restrict__ Wq, const float* __restrict__ Wk,
    const float* __restrict__ Wv, const float* __restrict__ Wo,
    __half* __restrict__ hf, __half* __restrict__ wf)
{
    int i = blockIdx.x * blockDim.x + threadIdx.x;
    const float* src;
    __half* dst;
    int j;
    if (i < HN4) {
        src = h; dst = hf; j = i;
    } else {
        int w = (i - HN4) >> 18;            // / WN4 (=262144)
        j = (i - HN4) & (WN4 - 1);
        src = (w == 0) ? Wq : (w == 1) ? Wk : (w == 2) ? Wv : Wo;
        dst = wf + (size_t)w * DD * DD;
    }
    float4 v = ((const float4*)src)[j];
    uint2 f4;
    f4.x = packf16(v.x, v.y); f4.y = packf16(v.z, v.w);
    ((uint2*)dst)[j] = f4;
}

// ===========================================================================
// fp16 NT GEMM: C[m,n] = sum_k A[m,k]*W[n,k] + bias[n]
// 128x128x(BK=64) tile, 8 warps 4m x 2n, 3-stage cp.async, 2 CTAs/SM.
// Inner loop: batch ALL ldsm (2 A + 4 B) per k-step, then 16 MMAs.
// mode 0: head-major fp16 store (z: 0=q scaled, 1=k, 2=v)
// mode 1: fp32 [row,col] store to fout.
// ===========================================================================
#define G_A 0
#define G_B 16384
#define G_STAGE 32768
#define G_SMEM  (3 * G_STAGE)          /* 98304 */

__global__ __launch_bounds__(256, 2) void gemm_f16(
    const __half* __restrict__ A, const __half* __restrict__ Wbase,
    const float* __restrict__ b0p, const float* __restrict__ b1p,
    const float* __restrict__ b2p,
    __half* d0, __half* d1, __half* d2,
    float* fout, int mode)
{
    extern __shared__ char sh[];
    const uint32_t shb = smem_u32(sh);
    const int tid  = threadIdx.x;
    const int lane = tid & 31;
    const int wid  = tid >> 5;
    const int wm   = wid & 3;
    const int wn   = wid >> 2;
    const int m0   = blockIdx.y * 128;
    const int n0   = blockIdx.x * 128;
    const int z    = blockIdx.z;

    const __half* W = Wbase + (size_t)z * DD * DD;
    const float* bias = (z == 0) ? b0p : (z == 1) ? b1p : b2p;

    const int frow = tid >> 1;
    const int cb   = (tid & 1) * 4;

    float acc[2][8][4];
#pragma unroll
    for (int mt = 0; mt < 2; ++mt)
#pragma unroll
        for (int nt = 0; nt < 8; ++nt)
#pragma unroll
            for (int e = 0; e < 4; ++e) acc[mt][nt][e] = 0.0f;

    auto fill = [&](int st, int kb) {
        uint32_t sb = shb + st * G_STAGE;
        size_t ga = (size_t)(m0 + frow) * DD + kb * 64;
        size_t gb = (size_t)(n0 + frow) * DD + kb * 64;
#pragma unroll
        for (int ci = 0; ci < 4; ++ci) {
            int c = cb + ci;
            uint32_t off = (uint32_t)frow * 128 + (((uint32_t)(c ^ (frow & 7))) << 4);
            cpa16(sb + G_A + off, A + ga + c * 8);
            cpa16(sb + G_B + off, W + gb + c * 8);
        }
    };

    fill(0, 0); CP_COMMIT();
    fill(1, 1); CP_COMMIT();

    const int KB = DD / 64;   // 16
    int st = 0;
    for (int kb = 0; kb < KB; ++kb) {
        if (kb + 2 < KB) CP_WAIT(1); else CP_WAIT(0);
        __syncthreads();
        if (kb + 2 < KB) { fill((st + 2) % 3, kb + 2); CP_COMMIT(); }

        const uint32_t sb = shb + st * G_STAGE;
#pragma unroll
        for (int ks = 0; ks < 4; ++ks) {
            // ---- batch ALL smem loads for this k-step ----
            uint32_t af[2][4], bf[4][4];
#pragma unroll
            for (int mt = 0; mt < 2; ++mt) {
                int r = wm * 32 + mt * 16 + (lane & 15);
                int g = ks * 2 + (lane >> 4);
                uint32_t off = (uint32_t)r * 128 + (((uint32_t)(g ^ (r & 7))) << 4);
                ldsm4(af[mt], sb + G_A + off);
            }
#pragma unroll
            for (int np = 0; np < 4; ++np) {
                int r = wn * 64 + np * 16 + ((lane >> 4) << 3) + (lane & 7);
                int g = ks * 2 + ((lane >> 3) & 1);
                uint32_t off = (uint32_t)r * 128 + (((uint32_t)(g ^ (r & 7))) << 4);
                ldsm4(bf[np], sb + G_B + off);
            }
            // ---- dense MMA burst (16 independent HMMAs) ----
#pragma unroll
            for (int np = 0; np < 4; ++np)
#pragma unroll
                for (int mt = 0; mt < 2; ++mt)
#pragma unroll
                    for (int t = 0; t < 2; ++t)
                        mma_f16(acc[mt][np * 2 + t], af[mt], bf[np] + t * 2);
        }
        st = (st + 1) % 3;
    }

    // ---- epilogue ----
    const float scale = (mode == 0 && z == 0) ? QSCALE : 1.0f;
    __half* dst = (z == 0) ? d0 : (z == 1) ? d1 : d2;
#pragma unroll
    for (int mt = 0; mt < 2; ++mt) {
        int r0 = m0 + wm * 32 + mt * 16 + (lane >> 2);
        int r1 = r0 + 8;
#pragma unroll
        for (int nt = 0; nt < 8; ++nt) {
            int col = n0 + wn * 64 + nt * 8 + ((lane & 3) << 1);
            float2 bv = *(const float2*)&bias[col];
            float v0x = (acc[mt][nt][0] + bv.x) * scale;
            float v0y = (acc[mt][nt][1] + bv.y) * scale;
            float v1x = (acc[mt][nt][2] + bv.x) * scale;
            float v1y = (acc[mt][nt][3] + bv.y) * scale;
            if (mode == 0) {
                int h_ = col >> 6, hd = col & 63;
                int b0 = r0 >> 11, ss0 = r0 & 2047;
                int b1 = r1 >> 11, ss1 = r1 & 2047;
                size_t i0 = ((size_t)(b0 * HH + h_) * SS + ss0) * HD + hd;
                size_t i1 = ((size_t)(b1 * HH + h_) * SS + ss1) * HD + hd;
                *(uint32_t*)&dst[i0] = packf16(v0x, v0y);
                *(uint32_t*)&dst[i1] = packf16(v1x, v1y);
            } else {
                float2 o0 = { v0x, v0y }, o1 = { v1x, v1y };
                *(float2*)&fout[(size_t)r0 * DD + col] = o0;
                *(float2*)&fout[(size_t)r1 * DD + col] = o1;
            }
        }
    }
}

// ===========================================================================
// Flash attention, all fp16 single-MMA. Block = (b,h) x 128 q-rows, 8 warps.
// 3-stage K/V pipeline (16KB/stage), 2 CTAs/SM, LPT tile order.
// QK and PV phases batch all 4 ldsm before the 8-MMA bursts.
// ===========================================================================
#define A_Q  0
#define A_K  0
#define A_V  8192
#define A_STAGE 16384
#define A_STB   16384
#define A_SMEM  (A_STB + 3 * A_STAGE)  /* 65536 */

__global__ __launch_bounds__(256, 2) void attn_f16()
{
    extern __shared__ char sh[];
    const uint32_t shb = smem_u32(sh);
    const int tid  = threadIdx.x;
    const int lane = tid & 31;
    const int wid  = tid >> 5;
    const int qt   = (int)gridDim.x - 1 - (int)blockIdx.x;   // heavy tiles first
    const int bh   = blockIdx.y;
    const int q0   = qt * 128;

    const __half* q_g = s_q + (size_t)bh * SS * HD;
    const __half* k_g = s_k + (size_t)bh * SS * HD;
    const __half* v_g = s_v + (size_t)bh * SS * HD;

    // ---- stage Q, ldsm to registers ----
    {
        int row = tid >> 1;
        int cb  = (tid & 1) * 4;
        size_t g = (size_t)(q0 + row) * HD;
#pragma unroll
        for (int ci = 0; ci < 4; ++ci) {
            int c = cb + ci;
            uint32_t off = (uint32_t)row * 128 + (((uint32_t)(c ^ (row & 7))) << 4);
            cpa16(shb + A_Q + off, q_g + g + c * 8);
        }
    }
    CP_COMMIT();
    CP_WAIT(0);
    __syncthreads();

    uint32_t qf[4][4];
#pragma unroll
    for (int ks = 0; ks < 4; ++ks) {
        int r = wid * 16 + (lane & 15);
        int g = ks * 2 + (lane >> 4);
        uint32_t off = (uint32_t)r * 128 + (((uint32_t)(g ^ (r & 7))) << 4);
        ldsm4(qf[ks], shb + A_Q + off);
    }

    float o[8][4];
#pragma unroll
    for (int nt = 0; nt < 8; ++nt)
#pragma unroll
        for (int e = 0; e < 4; ++e) o[nt][e] = 0.0f;
    float m0r = -1e30f, m1r = -1e30f, l0r = 0.0f, l1r = 0.0f;

    const int frow = tid >> 2;              // 0..63 key row
    const int fcb  = (tid & 3) * 2;

    auto fillkv = [&](int st, int kt) {
        uint32_t sb = shb + A_STB + st * A_STAGE;
        size_t g = (size_t)(kt * 64 + frow) * HD;
#pragma unroll
        for (int ci = 0; ci < 2; ++ci) {
            int c = fcb + ci;
            uint32_t off = (uint32_t)frow * 128 + (((uint32_t)(c ^ (frow & 7))) << 4);
            cpa16(sb + A_K + off, k_g + g + c * 8);
            cpa16(sb + A_V + off, v_g + g + c * 8);
        }
    };

    const int ktmax = 2 * qt + 2;
    const int warp_last_row = q0 + wid * 16 + 15;

    fillkv(0, 0); CP_COMMIT();
    fillkv(1, 1); CP_COMMIT();

    int st = 0;
    for (int kt = 0; kt < ktmax; ++kt) {
        if (kt + 2 < ktmax) CP_WAIT(1); else CP_WAIT(0);
        __syncthreads();
        if (kt + 2 < ktmax) { fillkv((st + 2) % 3, kt + 2); CP_COMMIT(); }

        const int k0g = kt * 64;
        if (k0g <= warp_last_row) {
            const uint32_t sb = shb + A_STB + st * A_STAGE;

            // ---- S = Q K^T (batched ldsm per k-step) ----
            float s[8][4];
#pragma unroll
            for (int nt = 0; nt < 8; ++nt)
#pragma unroll
                for (int e = 0; e < 4; ++e) s[nt][e] = 0.0f;

#pragma unroll
            for (int ks = 0; ks < 4; ++ks) {
                uint32_t kf[4][4];
#pragma unroll
                for (int np = 0; np < 4; ++np) {
                    int r = np * 16 + ((lane >> 4) << 3) + (lane & 7);
                    int g = ks * 2 + ((lane >> 3) & 1);
                    uint32_t off = (uint32_t)r * 128 + (((uint32_t)(g ^ (r & 7))) << 4);
                    ldsm4(kf[np], sb + A_K + off);
                }
#pragma unroll
                for (int np = 0; np < 4; ++np)
#pragma unroll
                    for (int t = 0; t < 2; ++t)
                        mma_f16(s[np * 2 + t], qf[ks], kf[np] + t * 2);
            }

            const int r0g = q0 + wid * 16 + (lane >> 2);
            const int r1g = r0g + 8;
            if (k0g + 63 > r0g) {
#pragma unroll
                for (int nt = 0; nt < 8; ++nt)
#pragma unroll
                    for (int e = 0; e < 2; ++e) {
                        int col = k0g + nt * 8 + ((lane & 3) << 1) + e;
                        if (col > r0g) s[nt][e]     = -1e30f;
                        if (col > r1g) s[nt][2 + e] = -1e30f;
                    }
            }

            // ---- online softmax (exp2 domain) ----
            float mx0 = -1e30f, mx1 = -1e30f;
#pragma unroll
            for (int nt = 0; nt < 8; ++nt) {
                mx0 = fmaxf(mx0, fmaxf(s[nt][0], s[nt][1]));
                mx1 = fmaxf(mx1, fmaxf(s[nt][2], s[nt][3]));
            }
            mx0 = fmaxf(mx0, __shfl_xor_sync(0xffffffffu, mx0, 1));
            mx0 = fmaxf(mx0, __shfl_xor_sync(0xffffffffu, mx0, 2));
            mx1 = fmaxf(mx1, __shfl_xor_sync(0xffffffffu, mx1, 1));
            mx1 = fmaxf(mx1, __shfl_xor_sync(0xffffffffu, mx1, 2));
            float mn0 = fmaxf(m0r, mx0), mn1 = fmaxf(m1r, mx1);
            float a0 = exp2f(m0r - mn0), a1 = exp2f(m1r - mn1);
            m0r = mn0; m1r = mn1;

            float sum0 = 0.0f, sum1 = 0.0f;
#pragma unroll
            for (int nt = 0; nt < 8; ++nt) {
                s[nt][0] = exp2f(s[nt][0] - mn0); sum0 += s[nt][0];
                s[nt][1] = exp2f(s[nt][1] - mn0); sum0 += s[nt][1];
                s[nt][2] = exp2f(s[nt][2] - mn1); sum1 += s[nt][2];
                s[nt][3] = exp2f(s[nt][3] - mn1); sum1 += s[nt][3];
            }
            sum0 += __shfl_xor_sync(0xffffffffu, sum0, 1);
            sum0 += __shfl_xor_sync(0xffffffffu, sum0, 2);
            sum1 += __shfl_xor_sync(0xffffffffu, sum1, 1);
            sum1 += __shfl_xor_sync(0xffffffffu, sum1, 2);
            l0r = l0r * a0 + sum0;
            l1r = l1r * a1 + sum1;
#pragma unroll
            for (int nt = 0; nt < 8; ++nt) {
                o[nt][0] *= a0; o[nt][1] *= a0;
                o[nt][2] *= a1; o[nt][3] *= a1;
            }

            // ---- O += P V (batched ldsm per j-step) ----
#pragma unroll
            for (int j = 0; j < 4; ++j) {
                uint32_t ph[4];
#pragma unroll
                for (int t = 0; t < 2; ++t) {
                    int nt = j * 2 + t;
                    ph[t * 2 + 0] = packf16(s[nt][0], s[nt][1]);
                    ph[t * 2 + 1] = packf16(s[nt][2], s[nt][3]);
                }
                uint32_t vf[4][4];
#pragma unroll
                for (int np = 0; np < 4; ++np) {
                    int r = j * 16 + (lane & 15);
                    int g = np * 2 + (lane >> 4);
                    uint32_t off = (uint32_t)r * 128 + (((uint32_t)(g ^ (r & 7))) << 4);
                    ldsm4t(vf[np], sb + A_V + off);
                }
#pragma unroll
                for (int np = 0; np < 4; ++np)
#pragma unroll
                    for (int t = 0; t < 2; ++t)
                        mma_f16(o[np * 2 + t], ph, vf[np] + t * 2);
            }
        }
        st = (st + 1) % 3;
    }

    // ---- normalize, write fp16 [B,S,D] ----
    const float inv0 = 1.0f / l0r;
    const float inv1 = 1.0f / l1r;
    const int b  = bh >> 4;
    const int h_ = bh & 15;
    const int r0 = q0 + wid * 16 + (lane >> 2);
    size_t base0 = ((size_t)b * SS + r0) * DD + h_ * 64;
    size_t base1 = base0 + (size_t)8 * DD;
#pragma unroll
    for (int nt = 0; nt < 8; ++nt) {
        int col = nt * 8 + ((lane & 3) << 1);
        *(uint32_t*)&s_a_f16[base0 + col] = packf16(o[nt][0] * inv0, o[nt][1] * inv0);
        *(uint32_t*)&s_a_f16[base1 + col] = packf16(o[nt][2] * inv1, o[nt][3] * inv1);
    }
}

// ---------------------------------------------------------------------------
extern "C" void kernel_launch(void* const* d_in, const int* in_sizes, int n_in,
                              void* d_out, int out_size)
{
    const float* h  = (const float*)d_in[0];
    const float* Wq = (const float*)d_in[1];
    const float* bq = (const float*)d_in[2];
    const float* Wk = (const float*)d_in[3];
    const float* bk = (const float*)d_in[4];
    const float* Wv = (const float*)d_in[5];
    const float* bv = (const float*)d_in[6];
    const float* Wo = (const float*)d_in[7];
    const float* bo = (const float*)d_in[8];
    float* out = (float*)d_out;

    __half *hf, *wf, *qp, *kp, *vp, *af;
    cudaGetSymbolAddress((void**)&hf, s_h_f16);
    cudaGetSymbolAddress((void**)&wf, s_w_f16);
    cudaGetSymbolAddress((void**)&qp, s_q);
    cudaGetSymbolAddress((void**)&kp, s_k);
    cudaGetSymbolAddress((void**)&vp, s_v);
    cudaGetSymbolAddress((void**)&af, s_a_f16);

    cudaFuncSetAttribute(gemm_f16, cudaFuncAttributeMaxDynamicSharedMemorySize, G_SMEM);
    cudaFuncSetAttribute(attn_f16, cudaFuncAttributeMaxDynamicSharedMemorySize, A_SMEM);

    const int TOTAL4 = HN4 + 4 * WN4;
    split_all<<<TOTAL4 / 256, 256>>>(h, Wq, Wk, Wv, Wo, hf, wf);

    // QKV projection (z = 0,1,2)
    dim3 qkv_grid(DD / 128, (BB * SS) / 128, 3);
    gemm_f16<<<qkv_grid, 256, G_SMEM>>>(hf, wf, bq, bk, bv,
                                        qp, kp, vp, nullptr, 0);

    attn_f16<<<dim3(SS / 128, BB * HH), 256, A_SMEM>>>();

    // O projection (Wo at offset 3)
    dim3 o_grid(DD / 128, (BB * SS) / 128, 1);
    gemm_f16<<<o_grid, 256, G_SMEM>>>(af, wf + 3 * (size_t)DD * DD,
                                      bo, bo, bo,
                                      nullptr, nullptr, nullptr,
                                      out, 1);
}